// round 1
// baseline (speedup 1.0000x reference)
#include <cuda_runtime.h>

#define BATCH 8
#define T_SEQ 2048
#define DM 1024
#define DH 64
#define M_TOTAL (BATCH * T_SEQ)   // 16384

// Scratch for Q, K, V projections (device globals: no allocation allowed)
__device__ float g_q[M_TOTAL * DH];
__device__ float g_k[M_TOTAL * DH];
__device__ float g_v[M_TOTAL * DH];

// ---------------------------------------------------------------------------
// Kernel 1: fused QKV projection.  out[16384,64] = x[16384,1024] @ W[1024,64]
// blockIdx.y in {0,1,2} selects (Wq->g_q, Wk->g_k, Wv->g_v).
// Block tile 128(M) x 64(N), BK=32, 128 threads, 8x8 register tiles.
// ---------------------------------------------------------------------------
#define QKV_BM 128
#define QKV_BK 32

__global__ __launch_bounds__(128)
void qkv_kernel(const float* __restrict__ x,
                const float* __restrict__ Wq,
                const float* __restrict__ Wk,
                const float* __restrict__ Wv)
{
    __shared__ float As[QKV_BK][132];  // transposed x tile: [k][m], padded
    __shared__ float Bs[QKV_BK][68];   // W tile: [k][n], padded

    const float* W;
    float* out;
    if (blockIdx.y == 0)      { W = Wq; out = g_q; }
    else if (blockIdx.y == 1) { W = Wk; out = g_k; }
    else                      { W = Wv; out = g_v; }

    const int m0 = blockIdx.x * QKV_BM;
    const int t  = threadIdx.x;          // 0..127
    const int tx = t & 7;                // 8 column-groups of 8
    const int ty = t >> 3;               // 16 row-groups of 8

    float acc[8][8];
    #pragma unroll
    for (int i = 0; i < 8; i++)
        #pragma unroll
        for (int j = 0; j < 8; j++) acc[i][j] = 0.0f;

    for (int k0 = 0; k0 < DM; k0 += QKV_BK) {
        // Load x tile (128 rows x 32 k), coalesced 128B per row, transpose to As
        #pragma unroll
        for (int p = 0; p < 8; p++) {
            int r = p * 16 + (t >> 3);
            int c = (t & 7) * 4;
            float4 v = *(const float4*)&x[(size_t)(m0 + r) * DM + k0 + c];
            As[c + 0][r] = v.x;
            As[c + 1][r] = v.y;
            As[c + 2][r] = v.z;
            As[c + 3][r] = v.w;
        }
        // Load W tile (32 k x 64 n), fully coalesced
        #pragma unroll
        for (int p = 0; p < 4; p++) {
            int kk = p * 8 + (t >> 4);
            int n  = (t & 15) * 4;
            *(float4*)&Bs[kk][n] = *(const float4*)&W[(size_t)(k0 + kk) * DH + n];
        }
        __syncthreads();

        #pragma unroll
        for (int kk = 0; kk < QKV_BK; kk++) {
            float4 a0 = *(const float4*)&As[kk][ty * 8];
            float4 a1 = *(const float4*)&As[kk][ty * 8 + 4];
            float4 b0 = *(const float4*)&Bs[kk][tx * 8];
            float4 b1 = *(const float4*)&Bs[kk][tx * 8 + 4];
            float a[8] = {a0.x, a0.y, a0.z, a0.w, a1.x, a1.y, a1.z, a1.w};
            float b[8] = {b0.x, b0.y, b0.z, b0.w, b1.x, b1.y, b1.z, b1.w};
            #pragma unroll
            for (int i = 0; i < 8; i++)
                #pragma unroll
                for (int j = 0; j < 8; j++)
                    acc[i][j] = fmaf(a[i], b[j], acc[i][j]);
        }
        __syncthreads();
    }

    #pragma unroll
    for (int i = 0; i < 8; i++) {
        size_t row = (size_t)(m0 + ty * 8 + i);
        *(float4*)&out[row * DH + tx * 8] =
            make_float4(acc[i][0], acc[i][1], acc[i][2], acc[i][3]);
        *(float4*)&out[row * DH + tx * 8 + 4] =
            make_float4(acc[i][4], acc[i][5], acc[i][6], acc[i][7]);
    }
}

// ---------------------------------------------------------------------------
// Kernel 2: causal flash attention (fp32, online softmax).
// Grid: (16, 8).  Block j of batch b handles query tiles j and 31-j (BM=64)
// => every block does exactly 33 key-tile iterations (load-balanced causal).
// 256 threads, thread (tx,ty) owns a 4x4 micro-tile.
// Shared (dynamic, 69632B): Qs[d][i], Ks[d][j], Vs[j][d], Ps[i][j], pad 68.
// ---------------------------------------------------------------------------
#define SM_PAD 68
#define SM_TILE (64 * SM_PAD)

__global__ __launch_bounds__(256)
void attn_kernel(float* __restrict__ out)
{
    extern __shared__ float sm[];
    float* Qs = sm;                 // [d][i], pre-scaled by 1/sqrt(1024)
    float* Ks = Qs + SM_TILE;       // [d][j]
    float* Vs = Ks + SM_TILE;       // [j][d]
    float* Ps = Vs + SM_TILE;       // [i][j]

    const int batch = blockIdx.y;
    const int jb    = blockIdx.x;   // 0..15
    const int t  = threadIdx.x;
    const int tx = t & 15;          // key-col groups
    const int ty = t >> 4;          // query-row groups

    const size_t bb = (size_t)batch * T_SEQ * DH;

    const int ld_i  = t >> 2;        // loader row (0..63)
    const int ld_d0 = (t & 3) * 16;  // loader dim chunk

    #pragma unroll
    for (int pass = 0; pass < 2; pass++) {
        const int qt = (pass == 0) ? jb : 31 - jb;
        const int qbase = qt * 64;

        // ---- load Q tile, transposed + pre-scaled by 1/32 ----
        {
            const float* Qg = g_q + bb + (size_t)qbase * DH;
            #pragma unroll
            for (int p = 0; p < 4; p++) {
                float4 v = *(const float4*)&Qg[ld_i * DH + ld_d0 + p * 4];
                const float sc = 0.03125f;  // 1/sqrt(1024)
                Qs[(ld_d0 + p * 4 + 0) * SM_PAD + ld_i] = v.x * sc;
                Qs[(ld_d0 + p * 4 + 1) * SM_PAD + ld_i] = v.y * sc;
                Qs[(ld_d0 + p * 4 + 2) * SM_PAD + ld_i] = v.z * sc;
                Qs[(ld_d0 + p * 4 + 3) * SM_PAD + ld_i] = v.w * sc;
            }
        }

        float m[4], l[4], o[4][4];
        #pragma unroll
        for (int a = 0; a < 4; a++) {
            m[a] = -1e30f;
            l[a] = 0.0f;
            #pragma unroll
            for (int d = 0; d < 4; d++) o[a][d] = 0.0f;
        }
        __syncthreads();

        for (int kt = 0; kt <= qt; kt++) {
            const int kbase = kt * 64;
            // ---- load K (transposed) and V (natural) tiles ----
            {
                const float* Kg = g_k + bb + (size_t)kbase * DH;
                const float* Vg = g_v + bb + (size_t)kbase * DH;
                #pragma unroll
                for (int p = 0; p < 4; p++) {
                    float4 v = *(const float4*)&Kg[ld_i * DH + ld_d0 + p * 4];
                    Ks[(ld_d0 + p * 4 + 0) * SM_PAD + ld_i] = v.x;
                    Ks[(ld_d0 + p * 4 + 1) * SM_PAD + ld_i] = v.y;
                    Ks[(ld_d0 + p * 4 + 2) * SM_PAD + ld_i] = v.z;
                    Ks[(ld_d0 + p * 4 + 3) * SM_PAD + ld_i] = v.w;
                    float4 w = *(const float4*)&Vg[ld_i * DH + ld_d0 + p * 4];
                    *(float4*)&Vs[ld_i * SM_PAD + ld_d0 + p * 4] = w;
                }
            }
            __syncthreads();

            // ---- S = (Q/32) . K^T ----
            float s[4][4];
            #pragma unroll
            for (int a = 0; a < 4; a++)
                #pragma unroll
                for (int b = 0; b < 4; b++) s[a][b] = 0.0f;

            #pragma unroll 16
            for (int d = 0; d < 64; d++) {
                float4 a4 = *(const float4*)&Qs[d * SM_PAD + ty * 4];
                float4 b4 = *(const float4*)&Ks[d * SM_PAD + tx * 4];
                float av[4] = {a4.x, a4.y, a4.z, a4.w};
                float bv[4] = {b4.x, b4.y, b4.z, b4.w};
                #pragma unroll
                for (int a = 0; a < 4; a++)
                    #pragma unroll
                    for (int b = 0; b < 4; b++)
                        s[a][b] = fmaf(av[a], bv[b], s[a][b]);
            }

            // ---- causal mask (only the diagonal tile needs it) ----
            if (kt == qt) {
                #pragma unroll
                for (int a = 0; a < 4; a++)
                    #pragma unroll
                    for (int b = 0; b < 4; b++)
                        if (tx * 4 + b > ty * 4 + a) s[a][b] = -1e30f;
            }

            // ---- online softmax (row reductions across 16 tx lanes) ----
            #pragma unroll
            for (int a = 0; a < 4; a++) {
                float mt = fmaxf(fmaxf(s[a][0], s[a][1]), fmaxf(s[a][2], s[a][3]));
                #pragma unroll
                for (int off = 8; off > 0; off >>= 1)
                    mt = fmaxf(mt, __shfl_xor_sync(0xffffffffu, mt, off));
                float mn = fmaxf(m[a], mt);
                float f  = __expf(m[a] - mn);
                m[a] = mn;
                float lt = 0.0f;
                #pragma unroll
                for (int b = 0; b < 4; b++) {
                    float p = __expf(s[a][b] - mn);
                    s[a][b] = p;   // s now holds P
                    lt += p;
                }
                #pragma unroll
                for (int off = 8; off > 0; off >>= 1)
                    lt += __shfl_xor_sync(0xffffffffu, lt, off);
                l[a] = l[a] * f + lt;
                #pragma unroll
                for (int d = 0; d < 4; d++) o[a][d] *= f;
            }

            // ---- stage P to smem (natural [i][j]: conflict-free STS.128) ----
            #pragma unroll
            for (int a = 0; a < 4; a++)
                *(float4*)&Ps[(ty * 4 + a) * SM_PAD + tx * 4] =
                    make_float4(s[a][0], s[a][1], s[a][2], s[a][3]);
            __syncthreads();

            // ---- O += P . V ----
            #pragma unroll 16
            for (int jj = 0; jj < 64; jj++) {
                float4 b4 = *(const float4*)&Vs[jj * SM_PAD + tx * 4];
                float bv[4] = {b4.x, b4.y, b4.z, b4.w};
                #pragma unroll
                for (int a = 0; a < 4; a++) {
                    float pa = Ps[(ty * 4 + a) * SM_PAD + jj];  // broadcast read
                    #pragma unroll
                    for (int d = 0; d < 4; d++)
                        o[a][d] = fmaf(pa, bv[d], o[a][d]);
                }
            }
            __syncthreads();
        }

        // ---- epilogue: normalize and store ----
        #pragma unroll
        for (int a = 0; a < 4; a++) {
            float inv = 1.0f / l[a];
            size_t row = (size_t)(qbase + ty * 4 + a);
            *(float4*)&out[bb + row * DH + tx * 4] =
                make_float4(o[a][0] * inv, o[a][1] * inv,
                            o[a][2] * inv, o[a][3] * inv);
        }
        __syncthreads();   // protect smem before next pass reloads
    }
}

// ---------------------------------------------------------------------------
// Launch
// ---------------------------------------------------------------------------
extern "C" void kernel_launch(void* const* d_in, const int* in_sizes, int n_in,
                              void* d_out, int out_size)
{
    (void)in_sizes; (void)n_in; (void)out_size;
    const float* x  = (const float*)d_in[0];
    const float* Wq = (const float*)d_in[1];
    const float* Wk = (const float*)d_in[2];
    const float* Wv = (const float*)d_in[3];
    float* out = (float*)d_out;

    qkv_kernel<<<dim3(M_TOTAL / QKV_BM, 3), 128>>>(x, Wq, Wk, Wv);

    const int smem_bytes = 4 * SM_TILE * (int)sizeof(float);  // 69632
    cudaFuncSetAttribute(attn_kernel,
                         cudaFuncAttributeMaxDynamicSharedMemorySize,
                         smem_bytes);
    attn_kernel<<<dim3(16, BATCH), 256, smem_bytes>>>(out);
}

// round 4
// speedup vs baseline: 2.6646x; 2.6646x over previous
#include <cuda_runtime.h>
#include <cuda_fp16.h>
#include <cuda_bf16.h>
#include <cstdint>

#define BATCH 8
#define T_SEQ 2048
#define DM 1024
#define DH 64
#define M_TOTAL (BATCH * T_SEQ)   // 16384

// ---------------------------------------------------------------------------
// Device scratch (no allocation allowed)
// ---------------------------------------------------------------------------
__device__ __align__(16) __half g_q16[M_TOTAL * DH];  // pre-scaled by 1/32
__device__ __align__(16) __half g_k16[M_TOTAL * DH];
__device__ __align__(16) __half g_v16[M_TOTAL * DH];
// W in B-fragment order: [tn(24)][ktile(64)][lane(32)][reg(2)] of u32(bf16x2)
#define WF_FRAGS (24 * 64 * 32)
__device__ __align__(16) uint32_t g_wfh[WF_FRAGS * 2];
__device__ __align__(16) uint32_t g_wfl[WF_FRAGS * 2];

// ---------------------------------------------------------------------------
// Helpers — sm_80-level PTX ONLY (plain sm_103 target: no tcgen05/'a' features)
// ---------------------------------------------------------------------------
__device__ __forceinline__ uint32_t smem_u32(const void* p) {
    uint32_t a;
    asm("{ .reg .u64 t; cvta.to.shared.u64 t, %1; cvt.u32.u64 %0, t; }"
        : "=r"(a) : "l"(p));
    return a;
}
__device__ __forceinline__ void ldsm4(uint32_t r[4], uint32_t a) {
    asm volatile("ldmatrix.sync.aligned.m8n8.x4.shared.b16 {%0,%1,%2,%3}, [%4];"
                 : "=r"(r[0]), "=r"(r[1]), "=r"(r[2]), "=r"(r[3]) : "r"(a));
}
__device__ __forceinline__ void ldsm4t(uint32_t r[4], uint32_t a) {
    asm volatile("ldmatrix.sync.aligned.m8n8.x4.trans.shared.b16 {%0,%1,%2,%3}, [%4];"
                 : "=r"(r[0]), "=r"(r[1]), "=r"(r[2]), "=r"(r[3]) : "r"(a));
}
__device__ __forceinline__ void mma_bf16(float c[4], const uint32_t a[4],
                                         uint32_t b0, uint32_t b1) {
    asm volatile(
        "mma.sync.aligned.m16n8k16.row.col.f32.bf16.bf16.f32 "
        "{%0,%1,%2,%3}, {%4,%5,%6,%7}, {%8,%9}, {%0,%1,%2,%3};"
        : "+f"(c[0]), "+f"(c[1]), "+f"(c[2]), "+f"(c[3])
        : "r"(a[0]), "r"(a[1]), "r"(a[2]), "r"(a[3]), "r"(b0), "r"(b1));
}
__device__ __forceinline__ void mma_f16(float c[4], const uint32_t a[4],
                                        uint32_t b0, uint32_t b1) {
    asm volatile(
        "mma.sync.aligned.m16n8k16.row.col.f32.f16.f16.f32 "
        "{%0,%1,%2,%3}, {%4,%5,%6,%7}, {%8,%9}, {%0,%1,%2,%3};"
        : "+f"(c[0]), "+f"(c[1]), "+f"(c[2]), "+f"(c[3])
        : "r"(a[0]), "r"(a[1]), "r"(a[2]), "r"(a[3]), "r"(b0), "r"(b1));
}
__device__ __forceinline__ void bar_grp(int id) {
    asm volatile("bar.sync %0, %1;" :: "r"(id), "r"(128) : "memory");
}
__device__ __forceinline__ uint32_t pbf2(float a, float b) {  // low half = a
    return ((uint32_t)__bfloat16_as_ushort(__float2bfloat16(b)) << 16) |
           (uint32_t)__bfloat16_as_ushort(__float2bfloat16(a));
}
__device__ __forceinline__ uint32_t ph2(float a, float b) {   // low half = a
    __half2 h = __floats2half2_rn(a, b);
    return *reinterpret_cast<uint32_t*>(&h);
}

// ---------------------------------------------------------------------------
// Kernel 0: W -> B-fragment-ordered bf16 hi/lo.
// Fragment (tn, kt, lane): reg r packs W[k][n'], W[k+1][n'] (bf16x2) with
// k = kt*16 + (lane&3)*2 + r*8,  n' = tn*8 + lane/4
// (n' 0-63 -> Wq, 64-127 -> Wk, 128-191 -> Wv)
// ---------------------------------------------------------------------------
__global__ __launch_bounds__(256)
void wprep_kernel(const float* __restrict__ Wq, const float* __restrict__ Wk,
                  const float* __restrict__ Wv)
{
    int frag = blockIdx.x * 256 + threadIdx.x;
    if (frag >= WF_FRAGS) return;
    int lane = frag & 31, kt = (frag >> 5) & 63, tn = frag >> 11;
    int np = tn * 8 + (lane >> 2);
    const float* W = (np < 64) ? Wq : (np < 128 ? Wk : Wv);
    int n = np & 63;
    #pragma unroll
    for (int r = 0; r < 2; r++) {
        int k = kt * 16 + (lane & 3) * 2 + r * 8;
        float v0 = W[k * DH + n], v1 = W[(k + 1) * DH + n];
        float h0 = __bfloat162float(__float2bfloat16(v0));
        float h1 = __bfloat162float(__float2bfloat16(v1));
        g_wfh[frag * 2 + r] = pbf2(v0, v1);
        g_wfl[frag * 2 + r] = pbf2(v0 - h0, v1 - h1);
    }
}

// ---------------------------------------------------------------------------
// Kernel 1: QKV projection, bf16 hi/lo 3-product on mma.sync.
// 128 CTAs x 256 threads.  CTA tile 128(M) x 192(N), K=1024 in 16 chunks.
// Warp grid 2(m) x 4(n): each warp 4 m16-tiles x 6 n8-tiles.
// Outputs fp16: q (scaled 1/32), k, v.
// ---------------------------------------------------------------------------
__global__ __launch_bounds__(256)
void qkv_kernel(const float* __restrict__ x)
{
    __shared__ __nv_bfloat16 xh[128 * 72];   // stride 72 halves = 144B
    __shared__ __nv_bfloat16 xl[128 * 72];

    const int t = threadIdx.x, lane = t & 31, wid = t >> 5;
    const int wm = wid & 1, wn = wid >> 1;
    const int m0 = blockIdx.x * 128;
    const uint32_t sh = smem_u32(xh), sl = smem_u32(xl);

    float c[4][6][4];
    #pragma unroll
    for (int mi = 0; mi < 4; mi++)
        #pragma unroll
        for (int nj = 0; nj < 6; nj++)
            #pragma unroll
            for (int q = 0; q < 4; q++) c[mi][nj][q] = 0.0f;

    const int ld_row = t >> 1, ld_cb = (t & 1) * 32;

    for (int cc = 0; cc < 16; cc++) {
        const int k0 = cc * 64;
        __syncthreads();
        // x tile 128x64 -> bf16 hi/lo smem
        {
            const float* xr = x + (size_t)(m0 + ld_row) * DM + k0 + ld_cb;
            #pragma unroll
            for (int i = 0; i < 8; i++) {
                float4 v = *(const float4*)(xr + i * 4);
                float hx = __bfloat162float(__float2bfloat16(v.x));
                float hy = __bfloat162float(__float2bfloat16(v.y));
                float hz = __bfloat162float(__float2bfloat16(v.z));
                float hw = __bfloat162float(__float2bfloat16(v.w));
                int si = ld_row * 72 + ld_cb + i * 4;
                *(uint2*)&xh[si] = make_uint2(pbf2(v.x, v.y), pbf2(v.z, v.w));
                *(uint2*)&xl[si] = make_uint2(pbf2(v.x - hx, v.y - hy),
                                              pbf2(v.z - hz, v.w - hw));
            }
        }
        __syncthreads();

        #pragma unroll
        for (int kt = 0; kt < 4; kt++) {
            const int kkg = cc * 4 + kt;
            uint32_t ah[4][4], al[4][4];
            const uint32_t arow = wm * 64 + (lane & 7) + ((lane >> 3) & 1) * 8;
            const uint32_t acb = kt * 32 + (lane >> 4) * 16;   // bytes
            #pragma unroll
            for (int mi = 0; mi < 4; mi++) {
                ldsm4(ah[mi], sh + (arow + mi * 16) * 144 + acb);
                ldsm4(al[mi], sl + (arow + mi * 16) * 144 + acb);
            }
            uint32_t bh[6][2], bl[6][2];
            #pragma unroll
            for (int nj = 0; nj < 6; nj++) {
                size_t off = ((size_t)((wn * 6 + nj) * 64 + kkg) * 32 + lane) * 2;
                uint2 u = *(const uint2*)&g_wfh[off];
                uint2 v = *(const uint2*)&g_wfl[off];
                bh[nj][0] = u.x; bh[nj][1] = u.y;
                bl[nj][0] = v.x; bl[nj][1] = v.y;
            }
            #pragma unroll
            for (int mi = 0; mi < 4; mi++)
                #pragma unroll
                for (int nj = 0; nj < 6; nj++) {
                    mma_bf16(c[mi][nj], ah[mi], bh[nj][0], bh[nj][1]);
                    mma_bf16(c[mi][nj], ah[mi], bl[nj][0], bl[nj][1]);
                    mma_bf16(c[mi][nj], al[mi], bh[nj][0], bh[nj][1]);
                }
        }
    }

    // epilogue: fp32 frags -> fp16 q/k/v
    #pragma unroll
    for (int mi = 0; mi < 4; mi++) {
        int r0 = m0 + wm * 64 + mi * 16 + (lane >> 2);
        #pragma unroll
        for (int nj = 0; nj < 6; nj++) {
            int nc = wn * 48 + nj * 8;
            int sel = nc >> 6;
            int col = (nc & 63) + (lane & 3) * 2;
            __half* dst = (sel == 0) ? g_q16 : (sel == 1 ? g_k16 : g_v16);
            float sc = (sel == 0) ? 0.03125f : 1.0f;   // 1/sqrt(1024) = 2^-5
            *(__half2*)&dst[(size_t)r0 * DH + col] =
                __floats2half2_rn(c[mi][nj][0] * sc, c[mi][nj][1] * sc);
            *(__half2*)&dst[(size_t)(r0 + 8) * DH + col] =
                __floats2half2_rn(c[mi][nj][2] * sc, c[mi][nj][3] * sc);
        }
    }
}

// ---------------------------------------------------------------------------
// Kernel 2: causal flash attention on fp16 mma.sync.
// Grid (16, 8) x 256 threads = 2 independent 4-warp groups.
// Group g serially handles qt = 2*jb+g and 31-(2*jb+g): 33 iters per group.
// Warp w owns 16 query rows; each iter processes 64 keys.
// ---------------------------------------------------------------------------
#define ATT_STRIDE 72
#define ATT_TILE (64 * ATT_STRIDE)

__global__ __launch_bounds__(256)
void attn_kernel(float* __restrict__ out)
{
    extern __shared__ __half smh[];
    const int t = threadIdx.x, lane = t & 31, wid = t >> 5;
    const int g = wid >> 2, w = wid & 3, gt = t & 127;
    const int jb = blockIdx.x, b = blockIdx.y;
    const size_t bb = (size_t)b * T_SEQ * DH;
    const int tile0 = jb * 2 + g;   // 0..31

    __half* Qs = smh + g * (3 * ATT_TILE);
    __half* Ks = Qs + ATT_TILE;
    __half* Vs = Ks + ATT_TILE;
    const uint32_t sq = smem_u32(Qs), sk = smem_u32(Ks), sv = smem_u32(Vs);

    const int rl = lane >> 2;        // 0..7; thread rows rl, rl+8 (warp-local)
    const int cb = (lane & 3) * 2;

    #pragma unroll
    for (int pass = 0; pass < 2; pass++) {
        const int qt = (pass == 0) ? tile0 : 31 - tile0;
        const int qbase = qt * 64;

        // ---- load Q tile (fp16, pre-scaled) ----
        #pragma unroll
        for (int i = 0; i < 4; i++) {
            int flat = gt + i * 128;
            int r = flat >> 3, c8 = flat & 7;
            *(uint4*)&Qs[r * ATT_STRIDE + c8 * 8] =
                *(const uint4*)&g_q16[bb + (size_t)(qbase + r) * DH + c8 * 8];
        }
        bar_grp(1 + g);

        uint32_t qa[4][4];
        {
            const uint32_t r_ = w * 16 + (lane & 7) + ((lane >> 3) & 1) * 8;
            #pragma unroll
            for (int kt = 0; kt < 4; kt++)
                ldsm4(qa[kt], sq + r_ * 144 + (kt * 2 + (lane >> 4)) * 16);
        }

        float o[8][4];
        #pragma unroll
        for (int nd = 0; nd < 8; nd++)
            #pragma unroll
            for (int q = 0; q < 4; q++) o[nd][q] = 0.0f;
        float m0v = -1e30f, m1v = -1e30f, l0v = 0.0f, l1v = 0.0f;

        for (int kt_ = 0; kt_ <= qt; kt_++) {
            bar_grp(1 + g);   // prior iter's smem reads done
            #pragma unroll
            for (int i = 0; i < 4; i++) {
                int flat = gt + i * 128;
                int r = flat >> 3, c8 = flat & 7;
                size_t src = bb + (size_t)(kt_ * 64 + r) * DH + c8 * 8;
                *(uint4*)&Ks[r * ATT_STRIDE + c8 * 8] = *(const uint4*)&g_k16[src];
                *(uint4*)&Vs[r * ATT_STRIDE + c8 * 8] = *(const uint4*)&g_v16[src];
            }
            bar_grp(1 + g);

            // ---- S = Q . K^T ----
            float s[8][4];
            #pragma unroll
            for (int nt = 0; nt < 8; nt++) {
                #pragma unroll
                for (int q = 0; q < 4; q++) s[nt][q] = 0.0f;
                uint32_t kb[4];
                uint32_t base = sk + (nt * 8 + (lane & 7)) * 144;
                ldsm4(kb, base + (lane >> 3) * 16);          // d 0..31
                mma_f16(s[nt], qa[0], kb[0], kb[1]);
                mma_f16(s[nt], qa[1], kb[2], kb[3]);
                ldsm4(kb, base + (4 + (lane >> 3)) * 16);    // d 32..63
                mma_f16(s[nt], qa[2], kb[0], kb[1]);
                mma_f16(s[nt], qa[3], kb[2], kb[3]);
            }

            // ---- causal mask (diagonal tile only) ----
            if (kt_ == qt) {
                int r0 = w * 16 + rl, r1 = r0 + 8;
                #pragma unroll
                for (int nt = 0; nt < 8; nt++) {
                    int c0 = nt * 8 + cb;
                    if (c0     > r0) s[nt][0] = -1e30f;
                    if (c0 + 1 > r0) s[nt][1] = -1e30f;
                    if (c0     > r1) s[nt][2] = -1e30f;
                    if (c0 + 1 > r1) s[nt][3] = -1e30f;
                }
            }

            // ---- online softmax (reduce across 4-lane quad) ----
            float mt0 = -1e30f, mt1 = -1e30f;
            #pragma unroll
            for (int nt = 0; nt < 8; nt++) {
                mt0 = fmaxf(mt0, fmaxf(s[nt][0], s[nt][1]));
                mt1 = fmaxf(mt1, fmaxf(s[nt][2], s[nt][3]));
            }
            #pragma unroll
            for (int off = 1; off <= 2; off <<= 1) {
                mt0 = fmaxf(mt0, __shfl_xor_sync(0xffffffffu, mt0, off));
                mt1 = fmaxf(mt1, __shfl_xor_sync(0xffffffffu, mt1, off));
            }
            float mn0 = fmaxf(m0v, mt0), mn1 = fmaxf(m1v, mt1);
            float f0 = __expf(m0v - mn0), f1 = __expf(m1v - mn1);
            m0v = mn0; m1v = mn1;
            float lt0 = 0.0f, lt1 = 0.0f;
            #pragma unroll
            for (int nt = 0; nt < 8; nt++) {
                s[nt][0] = __expf(s[nt][0] - mn0); lt0 += s[nt][0];
                s[nt][1] = __expf(s[nt][1] - mn0); lt0 += s[nt][1];
                s[nt][2] = __expf(s[nt][2] - mn1); lt1 += s[nt][2];
                s[nt][3] = __expf(s[nt][3] - mn1); lt1 += s[nt][3];
            }
            #pragma unroll
            for (int off = 1; off <= 2; off <<= 1) {
                lt0 += __shfl_xor_sync(0xffffffffu, lt0, off);
                lt1 += __shfl_xor_sync(0xffffffffu, lt1, off);
            }
            l0v = l0v * f0 + lt0;
            l1v = l1v * f1 + lt1;
            #pragma unroll
            for (int nd = 0; nd < 8; nd++) {
                o[nd][0] *= f0; o[nd][1] *= f0;
                o[nd][2] *= f1; o[nd][3] *= f1;
            }

            // ---- O += P . V  (P: C-frag -> A-frag in registers) ----
            #pragma unroll
            for (int kk = 0; kk < 4; kk++) {
                uint32_t pa[4] = {
                    ph2(s[2 * kk][0],     s[2 * kk][1]),
                    ph2(s[2 * kk][2],     s[2 * kk][3]),
                    ph2(s[2 * kk + 1][0], s[2 * kk + 1][1]),
                    ph2(s[2 * kk + 1][2], s[2 * kk + 1][3])
                };
                uint32_t vbase = sv +
                    (kk * 16 + ((lane >> 3) & 1) * 8 + (lane & 7)) * 144 +
                    (lane >> 4) * 16;
                #pragma unroll
                for (int p = 0; p < 4; p++) {
                    uint32_t vb[4];
                    ldsm4t(vb, vbase + p * 32);
                    mma_f16(o[2 * p],     pa, vb[0], vb[1]);
                    mma_f16(o[2 * p + 1], pa, vb[2], vb[3]);
                }
            }
        }

        // ---- epilogue ----
        float inv0 = 1.0f / l0v, inv1 = 1.0f / l1v;
        int row0 = qbase + w * 16 + rl, row1 = row0 + 8;
        #pragma unroll
        for (int nd = 0; nd < 8; nd++) {
            int col = nd * 8 + cb;
            *(float2*)&out[bb + (size_t)row0 * DH + col] =
                make_float2(o[nd][0] * inv0, o[nd][1] * inv0);
            *(float2*)&out[bb + (size_t)row1 * DH + col] =
                make_float2(o[nd][2] * inv1, o[nd][3] * inv1);
        }
        bar_grp(1 + g);   // smem reads done before next pass overwrites
    }
}

// ---------------------------------------------------------------------------
// Launch
// ---------------------------------------------------------------------------
extern "C" void kernel_launch(void* const* d_in, const int* in_sizes, int n_in,
                              void* d_out, int out_size)
{
    (void)in_sizes; (void)n_in; (void)out_size;
    const float* x  = (const float*)d_in[0];
    const float* Wq = (const float*)d_in[1];
    const float* Wk = (const float*)d_in[2];
    const float* Wv = (const float*)d_in[3];
    float* out = (float*)d_out;

    wprep_kernel<<<WF_FRAGS / 256, 256>>>(Wq, Wk, Wv);
    qkv_kernel<<<M_TOTAL / 128, 256>>>(x);

    const int attn_smem = 2 * 3 * ATT_TILE * (int)sizeof(__half);  // 55296
    cudaFuncSetAttribute(attn_kernel,
                         cudaFuncAttributeMaxDynamicSharedMemorySize, attn_smem);
    attn_kernel<<<dim3(16, BATCH), 256, attn_smem>>>(out);
}

// round 5
// speedup vs baseline: 2.8913x; 1.0851x over previous
#include <cuda_runtime.h>
#include <cuda_fp16.h>
#include <cstdint>

#define BATCH 8
#define T_SEQ 2048
#define DM 1024
#define DH 64
#define M_TOTAL (BATCH * T_SEQ)   // 16384

// ---------------------------------------------------------------------------
// Device scratch (no allocation allowed)
// ---------------------------------------------------------------------------
__device__ __align__(16) __half g_q16[M_TOTAL * DH];  // pre-scaled by 1/32
__device__ __align__(16) __half g_k16[M_TOTAL * DH];
__device__ __align__(16) __half g_v16[M_TOTAL * DH];
// W in B-fragment order: [tn(24)][ktile(64)][lane(32)][reg(2)] of u32(fp16x2)
#define WF_FRAGS (24 * 64 * 32)
__device__ __align__(16) uint32_t g_wf[WF_FRAGS * 2];

// ---------------------------------------------------------------------------
// Helpers — sm_80-level PTX ONLY (plain sm_103 target: no 'a'-suffix features)
// ---------------------------------------------------------------------------
__device__ __forceinline__ uint32_t smem_u32(const void* p) {
    uint32_t a;
    asm("{ .reg .u64 t; cvta.to.shared.u64 t, %1; cvt.u32.u64 %0, t; }"
        : "=r"(a) : "l"(p));
    return a;
}
__device__ __forceinline__ void ldsm4(uint32_t r[4], uint32_t a) {
    asm volatile("ldmatrix.sync.aligned.m8n8.x4.shared.b16 {%0,%1,%2,%3}, [%4];"
                 : "=r"(r[0]), "=r"(r[1]), "=r"(r[2]), "=r"(r[3]) : "r"(a));
}
__device__ __forceinline__ void ldsm4t(uint32_t r[4], uint32_t a) {
    asm volatile("ldmatrix.sync.aligned.m8n8.x4.trans.shared.b16 {%0,%1,%2,%3}, [%4];"
                 : "=r"(r[0]), "=r"(r[1]), "=r"(r[2]), "=r"(r[3]) : "r"(a));
}
__device__ __forceinline__ void mma_f16(float c[4], const uint32_t a[4],
                                        uint32_t b0, uint32_t b1) {
    asm volatile(
        "mma.sync.aligned.m16n8k16.row.col.f32.f16.f16.f32 "
        "{%0,%1,%2,%3}, {%4,%5,%6,%7}, {%8,%9}, {%0,%1,%2,%3};"
        : "+f"(c[0]), "+f"(c[1]), "+f"(c[2]), "+f"(c[3])
        : "r"(a[0]), "r"(a[1]), "r"(a[2]), "r"(a[3]), "r"(b0), "r"(b1));
}
__device__ __forceinline__ uint32_t ph2(float a, float b) {   // low half = a
    __half2 h = __floats2half2_rn(a, b);
    return *reinterpret_cast<uint32_t*>(&h);
}

// ---------------------------------------------------------------------------
// Kernel 0: W -> B-fragment-ordered fp16.
// Fragment (tn, kt, lane): reg r packs W[k][n'], W[k+1][n'] (fp16x2) with
// k = kt*16 + (lane&3)*2 + r*8,  n' = tn*8 + lane/4
// (n' 0-63 -> Wq, 64-127 -> Wk, 128-191 -> Wv)
// ---------------------------------------------------------------------------
__global__ __launch_bounds__(256)
void wprep_kernel(const float* __restrict__ Wq, const float* __restrict__ Wk,
                  const float* __restrict__ Wv)
{
    int frag = blockIdx.x * 256 + threadIdx.x;
    if (frag >= WF_FRAGS) return;
    int lane = frag & 31, kt = (frag >> 5) & 63, tn = frag >> 11;
    int np = tn * 8 + (lane >> 2);
    const float* W = (np < 64) ? Wq : (np < 128 ? Wk : Wv);
    int n = np & 63;
    #pragma unroll
    for (int r = 0; r < 2; r++) {
        int k = kt * 16 + (lane & 3) * 2 + r * 8;
        g_wf[frag * 2 + r] = ph2(W[k * DH + n], W[(k + 1) * DH + n]);
    }
}

// ---------------------------------------------------------------------------
// Kernel 1: QKV projection, single fp16 product on mma.sync.
// 128 CTAs x 256 threads.  CTA tile 128(M) x 192(N), K=1024 in 16 chunks.
// Warp grid 2(m) x 4(n): each warp 4 m16-tiles x 6 n8-tiles.
// Outputs fp16: q (scaled 1/32), k, v.
// ---------------------------------------------------------------------------
__global__ __launch_bounds__(256)
void qkv_kernel(const float* __restrict__ x)
{
    __shared__ __half xs[128 * 72];   // stride 72 halves = 144B rows

    const int t = threadIdx.x, lane = t & 31, wid = t >> 5;
    const int wm = wid & 1, wn = wid >> 1;
    const int m0 = blockIdx.x * 128;
    const uint32_t sx = smem_u32(xs);

    float c[4][6][4];
    #pragma unroll
    for (int mi = 0; mi < 4; mi++)
        #pragma unroll
        for (int nj = 0; nj < 6; nj++)
            #pragma unroll
            for (int q = 0; q < 4; q++) c[mi][nj][q] = 0.0f;

    const int ld_row = t >> 1, ld_cb = (t & 1) * 32;

    for (int cc = 0; cc < 16; cc++) {
        const int k0 = cc * 64;
        __syncthreads();
        // x tile 128x64 fp32 -> fp16 smem
        {
            const float* xr = x + (size_t)(m0 + ld_row) * DM + k0 + ld_cb;
            #pragma unroll
            for (int i = 0; i < 4; i++) {
                float4 v0 = *(const float4*)(xr + i * 8);
                float4 v1 = *(const float4*)(xr + i * 8 + 4);
                int si = ld_row * 72 + ld_cb + i * 8;
                *(uint4*)&xs[si] = make_uint4(ph2(v0.x, v0.y), ph2(v0.z, v0.w),
                                              ph2(v1.x, v1.y), ph2(v1.z, v1.w));
            }
        }
        __syncthreads();

        #pragma unroll
        for (int kt = 0; kt < 4; kt++) {
            const int kkg = cc * 4 + kt;
            uint32_t ah[4][4];
            const uint32_t arow = wm * 64 + (lane & 7) + ((lane >> 3) & 1) * 8;
            const uint32_t acb = kt * 32 + (lane >> 4) * 16;   // bytes
            #pragma unroll
            for (int mi = 0; mi < 4; mi++)
                ldsm4(ah[mi], sx + (arow + mi * 16) * 144 + acb);

            uint32_t bf[6][2];
            #pragma unroll
            for (int nj = 0; nj < 6; nj++) {
                size_t off = ((size_t)((wn * 6 + nj) * 64 + kkg) * 32 + lane) * 2;
                uint2 u = *(const uint2*)&g_wf[off];
                bf[nj][0] = u.x; bf[nj][1] = u.y;
            }
            #pragma unroll
            for (int mi = 0; mi < 4; mi++)
                #pragma unroll
                for (int nj = 0; nj < 6; nj++)
                    mma_f16(c[mi][nj], ah[mi], bf[nj][0], bf[nj][1]);
        }
    }

    // epilogue: fp32 frags -> fp16 q/k/v
    #pragma unroll
    for (int mi = 0; mi < 4; mi++) {
        int r0 = m0 + wm * 64 + mi * 16 + (lane >> 2);
        #pragma unroll
        for (int nj = 0; nj < 6; nj++) {
            int nc = wn * 48 + nj * 8;
            int sel = nc >> 6;
            int col = (nc & 63) + (lane & 3) * 2;
            __half* dst = (sel == 0) ? g_q16 : (sel == 1 ? g_k16 : g_v16);
            float sc = (sel == 0) ? 0.03125f : 1.0f;   // 1/sqrt(1024) = 2^-5
            *(__half2*)&dst[(size_t)r0 * DH + col] =
                __floats2half2_rn(c[mi][nj][0] * sc, c[mi][nj][1] * sc);
            *(__half2*)&dst[(size_t)(r0 + 8) * DH + col] =
                __floats2half2_rn(c[mi][nj][2] * sc, c[mi][nj][3] * sc);
        }
    }
}

// ---------------------------------------------------------------------------
// Kernel 2: causal flash attention on fp16 mma.sync.
// Grid (32, 8) x 128 threads (one 4-warp group per CTA; 27.6KB smem ->
// multiple CTAs co-resident per SM, all 148 SMs covered).
// CTA tile0 serially handles qt = tile0 and 31-tile0: 33 iters total.
// Warp w owns 16 query rows; each iter processes 64 keys.
// ---------------------------------------------------------------------------
#define ATT_STRIDE 72
#define ATT_TILE (64 * ATT_STRIDE)

__global__ __launch_bounds__(128)
void attn_kernel(float* __restrict__ out)
{
    __shared__ __half Qs[ATT_TILE];
    __shared__ __half Ks[ATT_TILE];
    __shared__ __half Vs[ATT_TILE];

    const int t = threadIdx.x, lane = t & 31, w = t >> 5;
    const int tile0 = blockIdx.x, b = blockIdx.y;
    const size_t bb = (size_t)b * T_SEQ * DH;

    const uint32_t sq = smem_u32(Qs), sk = smem_u32(Ks), sv = smem_u32(Vs);
    const int rl = lane >> 2;        // 0..7; thread rows rl, rl+8 (warp-local)
    const int cb = (lane & 3) * 2;

    #pragma unroll
    for (int pass = 0; pass < 2; pass++) {
        const int qt = (pass == 0) ? tile0 : 31 - tile0;
        const int qbase = qt * 64;

        // ---- load Q tile (fp16, pre-scaled) ----
        #pragma unroll
        for (int i = 0; i < 4; i++) {
            int flat = t + i * 128;
            int r = flat >> 3, c8 = flat & 7;
            *(uint4*)&Qs[r * ATT_STRIDE + c8 * 8] =
                *(const uint4*)&g_q16[bb + (size_t)(qbase + r) * DH + c8 * 8];
        }
        __syncthreads();

        uint32_t qa[4][4];
        {
            const uint32_t r_ = w * 16 + (lane & 7) + ((lane >> 3) & 1) * 8;
            #pragma unroll
            for (int kt = 0; kt < 4; kt++)
                ldsm4(qa[kt], sq + r_ * 144 + (kt * 2 + (lane >> 4)) * 16);
        }

        float o[8][4];
        #pragma unroll
        for (int nd = 0; nd < 8; nd++)
            #pragma unroll
            for (int q = 0; q < 4; q++) o[nd][q] = 0.0f;
        float m0v = -1e30f, m1v = -1e30f, l0v = 0.0f, l1v = 0.0f;

        for (int kt_ = 0; kt_ <= qt; kt_++) {
            __syncthreads();   // prior iter's smem reads done
            #pragma unroll
            for (int i = 0; i < 4; i++) {
                int flat = t + i * 128;
                int r = flat >> 3, c8 = flat & 7;
                size_t src = bb + (size_t)(kt_ * 64 + r) * DH + c8 * 8;
                *(uint4*)&Ks[r * ATT_STRIDE + c8 * 8] = *(const uint4*)&g_k16[src];
                *(uint4*)&Vs[r * ATT_STRIDE + c8 * 8] = *(const uint4*)&g_v16[src];
            }
            __syncthreads();

            // ---- S = Q . K^T ----
            float s[8][4];
            #pragma unroll
            for (int nt = 0; nt < 8; nt++) {
                #pragma unroll
                for (int q = 0; q < 4; q++) s[nt][q] = 0.0f;
                uint32_t kb[4];
                uint32_t base = sk + (nt * 8 + (lane & 7)) * 144;
                ldsm4(kb, base + (lane >> 3) * 16);          // d 0..31
                mma_f16(s[nt], qa[0], kb[0], kb[1]);
                mma_f16(s[nt], qa[1], kb[2], kb[3]);
                ldsm4(kb, base + (4 + (lane >> 3)) * 16);    // d 32..63
                mma_f16(s[nt], qa[2], kb[0], kb[1]);
                mma_f16(s[nt], qa[3], kb[2], kb[3]);
            }

            // ---- causal mask (diagonal tile only) ----
            if (kt_ == qt) {
                int r0 = w * 16 + rl, r1 = r0 + 8;
                #pragma unroll
                for (int nt = 0; nt < 8; nt++) {
                    int c0 = nt * 8 + cb;
                    if (c0     > r0) s[nt][0] = -1e30f;
                    if (c0 + 1 > r0) s[nt][1] = -1e30f;
                    if (c0     > r1) s[nt][2] = -1e30f;
                    if (c0 + 1 > r1) s[nt][3] = -1e30f;
                }
            }

            // ---- online softmax (reduce across 4-lane quad) ----
            float mt0 = -1e30f, mt1 = -1e30f;
            #pragma unroll
            for (int nt = 0; nt < 8; nt++) {
                mt0 = fmaxf(mt0, fmaxf(s[nt][0], s[nt][1]));
                mt1 = fmaxf(mt1, fmaxf(s[nt][2], s[nt][3]));
            }
            #pragma unroll
            for (int off = 1; off <= 2; off <<= 1) {
                mt0 = fmaxf(mt0, __shfl_xor_sync(0xffffffffu, mt0, off));
                mt1 = fmaxf(mt1, __shfl_xor_sync(0xffffffffu, mt1, off));
            }
            float mn0 = fmaxf(m0v, mt0), mn1 = fmaxf(m1v, mt1);
            float f0 = __expf(m0v - mn0), f1 = __expf(m1v - mn1);
            m0v = mn0; m1v = mn1;
            float lt0 = 0.0f, lt1 = 0.0f;
            #pragma unroll
            for (int nt = 0; nt < 8; nt++) {
                s[nt][0] = __expf(s[nt][0] - mn0); lt0 += s[nt][0];
                s[nt][1] = __expf(s[nt][1] - mn0); lt0 += s[nt][1];
                s[nt][2] = __expf(s[nt][2] - mn1); lt1 += s[nt][2];
                s[nt][3] = __expf(s[nt][3] - mn1); lt1 += s[nt][3];
            }
            #pragma unroll
            for (int off = 1; off <= 2; off <<= 1) {
                lt0 += __shfl_xor_sync(0xffffffffu, lt0, off);
                lt1 += __shfl_xor_sync(0xffffffffu, lt1, off);
            }
            l0v = l0v * f0 + lt0;
            l1v = l1v * f1 + lt1;
            #pragma unroll
            for (int nd = 0; nd < 8; nd++) {
                o[nd][0] *= f0; o[nd][1] *= f0;
                o[nd][2] *= f1; o[nd][3] *= f1;
            }

            // ---- O += P . V  (P: C-frag -> A-frag in registers) ----
            #pragma unroll
            for (int kk = 0; kk < 4; kk++) {
                uint32_t pa[4] = {
                    ph2(s[2 * kk][0],     s[2 * kk][1]),
                    ph2(s[2 * kk][2],     s[2 * kk][3]),
                    ph2(s[2 * kk + 1][0], s[2 * kk + 1][1]),
                    ph2(s[2 * kk + 1][2], s[2 * kk + 1][3])
                };
                uint32_t vbase = sv +
                    (kk * 16 + ((lane >> 3) & 1) * 8 + (lane & 7)) * 144 +
                    (lane >> 4) * 16;
                #pragma unroll
                for (int p = 0; p < 4; p++) {
                    uint32_t vb[4];
                    ldsm4t(vb, vbase + p * 32);
                    mma_f16(o[2 * p],     pa, vb[0], vb[1]);
                    mma_f16(o[2 * p + 1], pa, vb[2], vb[3]);
                }
            }
        }

        // ---- epilogue ----
        float inv0 = 1.0f / l0v, inv1 = 1.0f / l1v;
        int row0 = qbase + w * 16 + rl, row1 = row0 + 8;
        #pragma unroll
        for (int nd = 0; nd < 8; nd++) {
            int col = nd * 8 + cb;
            *(float2*)&out[bb + (size_t)row0 * DH + col] =
                make_float2(o[nd][0] * inv0, o[nd][1] * inv0);
            *(float2*)&out[bb + (size_t)row1 * DH + col] =
                make_float2(o[nd][2] * inv1, o[nd][3] * inv1);
        }
        __syncthreads();   // smem reads done before next pass overwrites
    }
}

// ---------------------------------------------------------------------------
// Launch
// ---------------------------------------------------------------------------
extern "C" void kernel_launch(void* const* d_in, const int* in_sizes, int n_in,
                              void* d_out, int out_size)
{
    (void)in_sizes; (void)n_in; (void)out_size;
    const float* x  = (const float*)d_in[0];
    const float* Wq = (const float*)d_in[1];
    const float* Wk = (const float*)d_in[2];
    const float* Wv = (const float*)d_in[3];
    float* out = (float*)d_out;

    wprep_kernel<<<WF_FRAGS / 256, 256>>>(Wq, Wk, Wv);
    qkv_kernel<<<M_TOTAL / 128, 256>>>(x);
    attn_kernel<<<dim3(32, BATCH), 128>>>(out);
}

// round 6
// speedup vs baseline: 4.0267x; 1.3927x over previous
#include <cuda_runtime.h>
#include <cuda_fp16.h>
#include <cstdint>

#define BATCH 8
#define T_SEQ 2048
#define DM 1024
#define DH 64
#define M_TOTAL (BATCH * T_SEQ)   // 16384

// ---------------------------------------------------------------------------
// Device scratch (no allocation allowed)
// ---------------------------------------------------------------------------
__device__ __align__(16) __half g_q16[M_TOTAL * DH];  // pre-scaled by log2e/32
__device__ __align__(16) __half g_k16[M_TOTAL * DH];
__device__ __align__(16) __half g_v16[M_TOTAL * DH];
// W in B-fragment order: [tn(24)][ktile(64)][lane(32)][reg(2)] of u32(fp16x2)
#define WF_FRAGS (24 * 64 * 32)
__device__ __align__(16) uint32_t g_wf[WF_FRAGS * 2];

// ---------------------------------------------------------------------------
// Helpers — sm_80-level PTX ONLY (plain sm_103 target: no 'a'-suffix features)
// ---------------------------------------------------------------------------
__device__ __forceinline__ uint32_t smem_u32(const void* p) {
    uint32_t a;
    asm("{ .reg .u64 t; cvta.to.shared.u64 t, %1; cvt.u32.u64 %0, t; }"
        : "=r"(a) : "l"(p));
    return a;
}
__device__ __forceinline__ void ldsm4(uint32_t r[4], uint32_t a) {
    asm volatile("ldmatrix.sync.aligned.m8n8.x4.shared.b16 {%0,%1,%2,%3}, [%4];"
                 : "=r"(r[0]), "=r"(r[1]), "=r"(r[2]), "=r"(r[3]) : "r"(a));
}
__device__ __forceinline__ void ldsm4t(uint32_t r[4], uint32_t a) {
    asm volatile("ldmatrix.sync.aligned.m8n8.x4.trans.shared.b16 {%0,%1,%2,%3}, [%4];"
                 : "=r"(r[0]), "=r"(r[1]), "=r"(r[2]), "=r"(r[3]) : "r"(a));
}
__device__ __forceinline__ void mma_f16(float c[4], const uint32_t a[4],
                                        uint32_t b0, uint32_t b1) {
    asm volatile(
        "mma.sync.aligned.m16n8k16.row.col.f32.f16.f16.f32 "
        "{%0,%1,%2,%3}, {%4,%5,%6,%7}, {%8,%9}, {%0,%1,%2,%3};"
        : "+f"(c[0]), "+f"(c[1]), "+f"(c[2]), "+f"(c[3])
        : "r"(a[0]), "r"(a[1]), "r"(a[2]), "r"(a[3]), "r"(b0), "r"(b1));
}
__device__ __forceinline__ uint32_t ph2(float a, float b) {   // low half = a
    __half2 h = __floats2half2_rn(a, b);
    return *reinterpret_cast<uint32_t*>(&h);
}
__device__ __forceinline__ float ex2(float x) {
    float y;
    asm("ex2.approx.f32 %0, %1;" : "=f"(y) : "f"(x));
    return y;
}
__device__ __forceinline__ void cpa16(uint32_t s, const void* g) {
    asm volatile("cp.async.cg.shared.global [%0], [%1], 16;"
                 :: "r"(s), "l"(g) : "memory");
}
#define CPA_COMMIT() asm volatile("cp.async.commit_group;" ::: "memory")
#define CPA_WAIT(n)  asm volatile("cp.async.wait_group %0;" :: "n"(n) : "memory")

// ---------------------------------------------------------------------------
// Kernel 0: W -> B-fragment-ordered fp16.
// Fragment (tn, kt, lane): reg r packs W[k][n'], W[k+1][n'] with
// k = kt*16 + (lane&3)*2 + r*8,  n' = tn*8 + lane/4
// (n' 0-63 -> Wq, 64-127 -> Wk, 128-191 -> Wv)
// ---------------------------------------------------------------------------
__global__ __launch_bounds__(256)
void wprep_kernel(const float* __restrict__ Wq, const float* __restrict__ Wk,
                  const float* __restrict__ Wv)
{
    int frag = blockIdx.x * 256 + threadIdx.x;
    if (frag >= WF_FRAGS) return;
    int lane = frag & 31, kt = (frag >> 5) & 63, tn = frag >> 11;
    int np = tn * 8 + (lane >> 2);
    const float* W = (np < 64) ? Wq : (np < 128 ? Wk : Wv);
    int n = np & 63;
    #pragma unroll
    for (int r = 0; r < 2; r++) {
        int k = kt * 16 + (lane & 3) * 2 + r * 8;
        g_wf[frag * 2 + r] = ph2(W[k * DH + n], W[(k + 1) * DH + n]);
    }
}

// ---------------------------------------------------------------------------
// Kernel 1: QKV projection, fp16 mma.sync, latency-hidden.
// 256 CTAs x 128 threads.  CTA tile 64(M) x 192(N), K=1024 in 16 chunks.
// Register-staged x prefetch + double-buffered smem, ONE barrier per chunk.
// Warp wn handles all 64 rows (4 m16-tiles) x 48 cols (6 n8-tiles).
// Outputs fp16: q (scaled log2e/32), k, v.
// ---------------------------------------------------------------------------
__global__ __launch_bounds__(128)
void qkv_kernel(const float* __restrict__ x)
{
    __shared__ __half xs[2][64 * 72];    // 144B rows

    const int t = threadIdx.x, lane = t & 31, wn = t >> 5;
    const int m0 = blockIdx.x * 64;
    const uint32_t sxb[2] = {smem_u32(xs[0]), smem_u32(xs[1])};

    float c[4][6][4];
    #pragma unroll
    for (int mi = 0; mi < 4; mi++)
        #pragma unroll
        for (int nj = 0; nj < 6; nj++)
            #pragma unroll
            for (int q = 0; q < 4; q++) c[mi][nj][q] = 0.0f;

    const int ld_row = t >> 1, ld_cb = (t & 1) * 32;
    const float* xbase = x + (size_t)(m0 + ld_row) * DM + ld_cb;

    // prefetch chunk 0 into registers
    float4 xr[8];
    #pragma unroll
    for (int i = 0; i < 8; i++) xr[i] = *(const float4*)(xbase + i * 4);

    const uint32_t arow = (lane & 7) + ((lane >> 3) & 1) * 8;

    for (int cc = 0; cc < 16; cc++) {
        // stage registers -> fp16 smem (buffer cc&1)
        __half* xb = xs[cc & 1];
        #pragma unroll
        for (int i = 0; i < 4; i++) {
            float4 v0 = xr[2 * i], v1 = xr[2 * i + 1];
            *(uint4*)&xb[ld_row * 72 + ld_cb + i * 8] =
                make_uint4(ph2(v0.x, v0.y), ph2(v0.z, v0.w),
                           ph2(v1.x, v1.y), ph2(v1.z, v1.w));
        }
        __syncthreads();

        // issue next chunk's gmem loads (consumed next iteration)
        if (cc < 15) {
            const float* xp = xbase + (cc + 1) * 64;
            #pragma unroll
            for (int i = 0; i < 8; i++) xr[i] = *(const float4*)(xp + i * 4);
        }

        const uint32_t sx = sxb[cc & 1];
        #pragma unroll
        for (int kt = 0; kt < 4; kt++) {
            const int kkg = cc * 4 + kt;
            uint32_t ah[4][4];
            const uint32_t acb = kt * 32 + (lane >> 4) * 16;   // bytes
            #pragma unroll
            for (int mi = 0; mi < 4; mi++)
                ldsm4(ah[mi], sx + (arow + mi * 16) * 144 + acb);

            uint32_t bf[6][2];
            #pragma unroll
            for (int nj = 0; nj < 6; nj++) {
                size_t off = ((size_t)((wn * 6 + nj) * 64 + kkg) * 32 + lane) * 2;
                uint2 u = *(const uint2*)&g_wf[off];
                bf[nj][0] = u.x; bf[nj][1] = u.y;
            }
            #pragma unroll
            for (int mi = 0; mi < 4; mi++)
                #pragma unroll
                for (int nj = 0; nj < 6; nj++)
                    mma_f16(c[mi][nj], ah[mi], bf[nj][0], bf[nj][1]);
        }
    }

    // epilogue: fp32 frags -> fp16 q/k/v
    const float QSC = 0.03125f * 1.44269504088896f;  // (1/sqrt(1024))*log2(e)
    #pragma unroll
    for (int mi = 0; mi < 4; mi++) {
        int r0 = m0 + mi * 16 + (lane >> 2);
        #pragma unroll
        for (int nj = 0; nj < 6; nj++) {
            int nc = wn * 48 + nj * 8;
            int sel = nc >> 6;
            int col = (nc & 63) + (lane & 3) * 2;
            __half* dst = (sel == 0) ? g_q16 : (sel == 1 ? g_k16 : g_v16);
            float sc = (sel == 0) ? QSC : 1.0f;
            *(__half2*)&dst[(size_t)r0 * DH + col] =
                __floats2half2_rn(c[mi][nj][0] * sc, c[mi][nj][1] * sc);
            *(__half2*)&dst[(size_t)(r0 + 8) * DH + col] =
                __floats2half2_rn(c[mi][nj][2] * sc, c[mi][nj][3] * sc);
        }
    }
}

// ---------------------------------------------------------------------------
// Kernel 2: causal flash attention, fp16 mma.sync + cp.async double buffer.
// Grid (32, 8) x 128 threads.  CTA handles qt = tile0 then 31-tile0 (33 iters).
// Softmax in exp2 domain (q pre-scaled by log2e/32).
// ---------------------------------------------------------------------------
#define ATT_STRIDE 72
#define ATT_TILE (64 * ATT_STRIDE)

__global__ __launch_bounds__(128)
void attn_kernel(float* __restrict__ out)
{
    __shared__ __half Qs[ATT_TILE];
    __shared__ __half Ks[2][ATT_TILE];
    __shared__ __half Vs[2][ATT_TILE];

    const int t = threadIdx.x, lane = t & 31, w = t >> 5;
    const int tile0 = blockIdx.x, b = blockIdx.y;
    const size_t bb = (size_t)b * T_SEQ * DH;

    const uint32_t sq = smem_u32(Qs);
    const uint32_t skb[2] = {smem_u32(Ks[0]), smem_u32(Ks[1])};
    const uint32_t svb[2] = {smem_u32(Vs[0]), smem_u32(Vs[1])};
    const int rl = lane >> 2, cb = (lane & 3) * 2;

    // this thread's 4 slots within a 64x64 fp16 tile
    int srow[4], scol[4];
    #pragma unroll
    for (int i = 0; i < 4; i++) {
        int flat = t + i * 128;
        srow[i] = flat >> 3;
        scol[i] = (flat & 7) * 8;
    }

    #pragma unroll
    for (int pass = 0; pass < 2; pass++) {
        const int qt = (pass == 0) ? tile0 : 31 - tile0;
        const int qbase = qt * 64;

        // prologue group: Q tile + K/V tile 0
        #pragma unroll
        for (int i = 0; i < 4; i++) {
            size_t qsrc = bb + (size_t)(qbase + srow[i]) * DH + scol[i];
            cpa16(sq + (srow[i] * ATT_STRIDE + scol[i]) * 2, &g_q16[qsrc]);
            size_t ksrc = bb + (size_t)srow[i] * DH + scol[i];
            cpa16(skb[0] + (srow[i] * ATT_STRIDE + scol[i]) * 2, &g_k16[ksrc]);
            cpa16(svb[0] + (srow[i] * ATT_STRIDE + scol[i]) * 2, &g_v16[ksrc]);
        }
        CPA_COMMIT();

        uint32_t qa[4][4];
        float o[8][4];
        #pragma unroll
        for (int nd = 0; nd < 8; nd++)
            #pragma unroll
            for (int q = 0; q < 4; q++) o[nd][q] = 0.0f;
        float m0v = -1e30f, m1v = -1e30f, l0v = 0.0f, l1v = 0.0f;

        for (int kt_ = 0; kt_ <= qt; kt_++) {
            if (kt_ < qt) {
                // issue next K/V tile into other buffer
                uint32_t dk = skb[(kt_ + 1) & 1], dv = svb[(kt_ + 1) & 1];
                #pragma unroll
                for (int i = 0; i < 4; i++) {
                    size_t src = bb + (size_t)((kt_ + 1) * 64 + srow[i]) * DH + scol[i];
                    cpa16(dk + (srow[i] * ATT_STRIDE + scol[i]) * 2, &g_k16[src]);
                    cpa16(dv + (srow[i] * ATT_STRIDE + scol[i]) * 2, &g_v16[src]);
                }
                CPA_COMMIT();
                CPA_WAIT(1);   // current tile (and Q) landed
            } else {
                CPA_WAIT(0);
            }
            __syncthreads();

            if (kt_ == 0) {   // Q is resident now; build A-fragments once
                const uint32_t r_ = w * 16 + (lane & 7) + ((lane >> 3) & 1) * 8;
                #pragma unroll
                for (int kt = 0; kt < 4; kt++)
                    ldsm4(qa[kt], sq + r_ * 144 + (kt * 2 + (lane >> 4)) * 16);
            }

            const uint32_t sk = skb[kt_ & 1], sv = svb[kt_ & 1];

            // ---- S = Q . K^T  (log2-domain logits) ----
            float s[8][4];
            #pragma unroll
            for (int nt = 0; nt < 8; nt++) {
                #pragma unroll
                for (int q = 0; q < 4; q++) s[nt][q] = 0.0f;
                uint32_t kb[4];
                uint32_t base = sk + (nt * 8 + (lane & 7)) * 144;
                ldsm4(kb, base + (lane >> 3) * 16);          // d 0..31
                mma_f16(s[nt], qa[0], kb[0], kb[1]);
                mma_f16(s[nt], qa[1], kb[2], kb[3]);
                ldsm4(kb, base + (4 + (lane >> 3)) * 16);    // d 32..63
                mma_f16(s[nt], qa[2], kb[0], kb[1]);
                mma_f16(s[nt], qa[3], kb[2], kb[3]);
            }

            // ---- causal mask (diagonal tile only) ----
            if (kt_ == qt) {
                int r0 = w * 16 + rl, r1 = r0 + 8;
                #pragma unroll
                for (int nt = 0; nt < 8; nt++) {
                    int c0 = nt * 8 + cb;
                    if (c0     > r0) s[nt][0] = -1e30f;
                    if (c0 + 1 > r0) s[nt][1] = -1e30f;
                    if (c0     > r1) s[nt][2] = -1e30f;
                    if (c0 + 1 > r1) s[nt][3] = -1e30f;
                }
            }

            // ---- online softmax (exp2 domain; quad reduction) ----
            float mt0 = -1e30f, mt1 = -1e30f;
            #pragma unroll
            for (int nt = 0; nt < 8; nt++) {
                mt0 = fmaxf(mt0, fmaxf(s[nt][0], s[nt][1]));
                mt1 = fmaxf(mt1, fmaxf(s[nt][2], s[nt][3]));
            }
            #pragma unroll
            for (int off = 1; off <= 2; off <<= 1) {
                mt0 = fmaxf(mt0, __shfl_xor_sync(0xffffffffu, mt0, off));
                mt1 = fmaxf(mt1, __shfl_xor_sync(0xffffffffu, mt1, off));
            }
            float mn0 = fmaxf(m0v, mt0), mn1 = fmaxf(m1v, mt1);
            float f0 = ex2(m0v - mn0), f1 = ex2(m1v - mn1);
            m0v = mn0; m1v = mn1;
            float lt0 = 0.0f, lt1 = 0.0f;
            #pragma unroll
            for (int nt = 0; nt < 8; nt++) {
                s[nt][0] = ex2(s[nt][0] - mn0); lt0 += s[nt][0];
                s[nt][1] = ex2(s[nt][1] - mn0); lt0 += s[nt][1];
                s[nt][2] = ex2(s[nt][2] - mn1); lt1 += s[nt][2];
                s[nt][3] = ex2(s[nt][3] - mn1); lt1 += s[nt][3];
            }
            #pragma unroll
            for (int off = 1; off <= 2; off <<= 1) {
                lt0 += __shfl_xor_sync(0xffffffffu, lt0, off);
                lt1 += __shfl_xor_sync(0xffffffffu, lt1, off);
            }
            l0v = l0v * f0 + lt0;
            l1v = l1v * f1 + lt1;
            #pragma unroll
            for (int nd = 0; nd < 8; nd++) {
                o[nd][0] *= f0; o[nd][1] *= f0;
                o[nd][2] *= f1; o[nd][3] *= f1;
            }

            // ---- O += P . V  (P: C-frag -> A-frag in registers) ----
            #pragma unroll
            for (int kk = 0; kk < 4; kk++) {
                uint32_t pa[4] = {
                    ph2(s[2 * kk][0],     s[2 * kk][1]),
                    ph2(s[2 * kk][2],     s[2 * kk][3]),
                    ph2(s[2 * kk + 1][0], s[2 * kk + 1][1]),
                    ph2(s[2 * kk + 1][2], s[2 * kk + 1][3])
                };
                uint32_t vbase = sv +
                    (kk * 16 + ((lane >> 3) & 1) * 8 + (lane & 7)) * 144 +
                    (lane >> 4) * 16;
                #pragma unroll
                for (int p = 0; p < 4; p++) {
                    uint32_t vb[4];
                    ldsm4t(vb, vbase + p * 32);
                    mma_f16(o[2 * p],     pa, vb[0], vb[1]);
                    mma_f16(o[2 * p + 1], pa, vb[2], vb[3]);
                }
            }
            __syncthreads();   // reads done before next iter's cp.async overwrite
        }

        // ---- epilogue ----
        float inv0 = 1.0f / l0v, inv1 = 1.0f / l1v;
        int row0 = qbase + w * 16 + rl, row1 = row0 + 8;
        #pragma unroll
        for (int nd = 0; nd < 8; nd++) {
            int col = nd * 8 + cb;
            *(float2*)&out[bb + (size_t)row0 * DH + col] =
                make_float2(o[nd][0] * inv0, o[nd][1] * inv0);
            *(float2*)&out[bb + (size_t)row1 * DH + col] =
                make_float2(o[nd][2] * inv1, o[nd][3] * inv1);
        }
        // trailing __syncthreads of the last iteration already protects Qs/Ks/Vs
    }
}

// ---------------------------------------------------------------------------
// Launch
// ---------------------------------------------------------------------------
extern "C" void kernel_launch(void* const* d_in, const int* in_sizes, int n_in,
                              void* d_out, int out_size)
{
    (void)in_sizes; (void)n_in; (void)out_size;
    const float* x  = (const float*)d_in[0];
    const float* Wq = (const float*)d_in[1];
    const float* Wk = (const float*)d_in[2];
    const float* Wv = (const float*)d_in[3];
    float* out = (float*)d_out;

    wprep_kernel<<<WF_FRAGS / 256, 256>>>(Wq, Wk, Wv);
    qkv_kernel<<<M_TOTAL / 64, 128>>>(x);
    attn_kernel<<<dim3(32, BATCH), 128>>>(out);
}

// round 7
// speedup vs baseline: 4.7919x; 1.1900x over previous
#include <cuda_runtime.h>
#include <cuda_fp16.h>
#include <cstdint>

#define BATCH 8
#define T_SEQ 2048
#define DM 1024
#define DH 64
#define M_TOTAL (BATCH * T_SEQ)   // 16384

// ---------------------------------------------------------------------------
// Device scratch (no allocation allowed)
// ---------------------------------------------------------------------------
__device__ __align__(16) __half g_q16[M_TOTAL * DH];  // pre-scaled by log2e/32
__device__ __align__(16) __half g_k16[M_TOTAL * DH];
__device__ __align__(16) __half g_v16[M_TOTAL * DH];
// W in B-fragment order: [tn(24)][ktile(64)][lane(32)][reg(2)] of u32(fp16x2)
#define WF_FRAGS (24 * 64 * 32)
__device__ __align__(16) uint32_t g_wf[WF_FRAGS * 2];

// ---------------------------------------------------------------------------
// Helpers — sm_80-level PTX ONLY (plain sm_103 target: no 'a'-suffix features)
// ---------------------------------------------------------------------------
__device__ __forceinline__ uint32_t smem_u32(const void* p) {
    uint32_t a;
    asm("{ .reg .u64 t; cvta.to.shared.u64 t, %1; cvt.u32.u64 %0, t; }"
        : "=r"(a) : "l"(p));
    return a;
}
__device__ __forceinline__ void ldsm4(uint32_t r[4], uint32_t a) {
    asm volatile("ldmatrix.sync.aligned.m8n8.x4.shared.b16 {%0,%1,%2,%3}, [%4];"
                 : "=r"(r[0]), "=r"(r[1]), "=r"(r[2]), "=r"(r[3]) : "r"(a));
}
__device__ __forceinline__ void ldsm4t(uint32_t r[4], uint32_t a) {
    asm volatile("ldmatrix.sync.aligned.m8n8.x4.trans.shared.b16 {%0,%1,%2,%3}, [%4];"
                 : "=r"(r[0]), "=r"(r[1]), "=r"(r[2]), "=r"(r[3]) : "r"(a));
}
__device__ __forceinline__ void mma_f16(float c[4], const uint32_t a[4],
                                        uint32_t b0, uint32_t b1) {
    asm volatile(
        "mma.sync.aligned.m16n8k16.row.col.f32.f16.f16.f32 "
        "{%0,%1,%2,%3}, {%4,%5,%6,%7}, {%8,%9}, {%0,%1,%2,%3};"
        : "+f"(c[0]), "+f"(c[1]), "+f"(c[2]), "+f"(c[3])
        : "r"(a[0]), "r"(a[1]), "r"(a[2]), "r"(a[3]), "r"(b0), "r"(b1));
}
__device__ __forceinline__ uint32_t ph2(float a, float b) {   // low half = a
    __half2 h = __floats2half2_rn(a, b);
    return *reinterpret_cast<uint32_t*>(&h);
}
__device__ __forceinline__ float ex2(float x) {
    float y;
    asm("ex2.approx.f32 %0, %1;" : "=f"(y) : "f"(x));
    return y;
}
__device__ __forceinline__ uint32_t hsub2_(uint32_t a, uint32_t b) {
    uint32_t d;
    asm("sub.f16x2 %0, %1, %2;" : "=r"(d) : "r"(a), "r"(b));
    return d;
}
__device__ __forceinline__ uint32_t h2ex2(uint32_t x) {
    uint32_t y;
    asm("ex2.approx.f16x2 %0, %1;" : "=r"(y) : "r"(x));
    return y;
}
__device__ __forceinline__ void cpa16(uint32_t s, const void* g) {
    asm volatile("cp.async.cg.shared.global [%0], [%1], 16;"
                 :: "r"(s), "l"(g) : "memory");
}
#define CPA_COMMIT() asm volatile("cp.async.commit_group;" ::: "memory")
#define CPA_WAIT(n)  asm volatile("cp.async.wait_group %0;" :: "n"(n) : "memory")

// ---------------------------------------------------------------------------
// Kernel 0: W -> B-fragment-ordered fp16 (coalesced reads, scattered writes).
// Fragment def: g_wf[((tn*64+kt)*32+lane)*2+r] = {W[k][n'], W[k+1][n']} with
// k = kt*16 + (lane&3)*2 + r*8,  n' = tn*8 + lane/4  (np 0-63 Wq, ... Wv)
// ---------------------------------------------------------------------------
__global__ __launch_bounds__(256)
void wprep_kernel(const float* __restrict__ Wq, const float* __restrict__ Wk,
                  const float* __restrict__ Wv)
{
    int tid = blockIdx.x * 256 + threadIdx.x;   // 24576 threads
    int nq = tid & 15, kp = (tid >> 4) & 511, m = tid >> 13;
    const float* W = (m == 0) ? Wq : (m == 1 ? Wk : Wv);
    int k = kp * 2, n0 = nq * 4;
    float4 a = *(const float4*)&W[k * DH + n0];
    float4 b = *(const float4*)&W[(k + 1) * DH + n0];
    int kt = k >> 4, r = (k >> 3) & 1, ksub = (k & 7) >> 1;
    const float* av = &a.x;
    const float* bv = &b.x;
    #pragma unroll
    for (int j = 0; j < 4; j++) {
        int np = m * 64 + n0 + j;
        int tn = np >> 3, lane = ((np & 7) << 2) | ksub;
        g_wf[(((size_t)tn * 64 + kt) * 32 + lane) * 2 + r] = ph2(av[j], bv[j]);
    }
}

// ---------------------------------------------------------------------------
// Kernel 1: QKV projection, fp16 mma.sync, latency-hidden.
// 512 CTAs x 128 threads.  CTA tile 32(M) x 192(N), K=1024 in 16 chunks.
// x: register prefetch + double-buffered smem, ONE barrier per chunk.
// W: B-fragments double-buffered in registers (prefetch next k-group).
// Outputs fp16: q (scaled log2e/32), k, v.
// ---------------------------------------------------------------------------
__global__ __launch_bounds__(128)
void qkv_kernel(const float* __restrict__ x)
{
    __shared__ __half xs[2][32 * 72];    // 144B rows

    const int t = threadIdx.x, lane = t & 31, wn = t >> 5;
    const int m0 = blockIdx.x * 32;
    const uint32_t sxb[2] = {smem_u32(xs[0]), smem_u32(xs[1])};

    float c[2][6][4];
    #pragma unroll
    for (int mi = 0; mi < 2; mi++)
        #pragma unroll
        for (int nj = 0; nj < 6; nj++)
            #pragma unroll
            for (int q = 0; q < 4; q++) c[mi][nj][q] = 0.0f;

    const int ld_row = t >> 2, ld_cb = (t & 3) * 16;
    const float* xbase = x + (size_t)(m0 + ld_row) * DM + ld_cb;

    // prefetch chunk 0 (x) into registers
    float4 xr[4];
    #pragma unroll
    for (int i = 0; i < 4; i++) xr[i] = *(const float4*)(xbase + i * 4);

    // prefetch k-group 0 (W fragments) into registers
    uint32_t bf[2][6][2];
    #pragma unroll
    for (int nj = 0; nj < 6; nj++) {
        uint2 u = *(const uint2*)&g_wf[((size_t)(wn * 6 + nj) * 64) * 64 + lane * 2];
        bf[0][nj][0] = u.x; bf[0][nj][1] = u.y;
    }

    const uint32_t arow = (lane & 7) + ((lane >> 3) & 1) * 8;

    for (int cc = 0; cc < 16; cc++) {
        // stage x registers -> fp16 smem (buffer cc&1)
        __half* xb = xs[cc & 1];
        #pragma unroll
        for (int i = 0; i < 2; i++) {
            float4 v0 = xr[2 * i], v1 = xr[2 * i + 1];
            *(uint4*)&xb[ld_row * 72 + ld_cb + i * 8] =
                make_uint4(ph2(v0.x, v0.y), ph2(v0.z, v0.w),
                           ph2(v1.x, v1.y), ph2(v1.z, v1.w));
        }
        __syncthreads();

        // issue next chunk's x loads (consumed next iteration)
        if (cc < 15) {
            const float* xp = xbase + (cc + 1) * 64;
            #pragma unroll
            for (int i = 0; i < 4; i++) xr[i] = *(const float4*)(xp + i * 4);
        }

        const uint32_t sx = sxb[cc & 1];
        #pragma unroll
        for (int kt = 0; kt < 4; kt++) {
            const int kkg = cc * 4 + kt;
            // prefetch next k-group's W fragments
            if (kkg < 63) {
                int nb = (kkg + 1) & 1;
                #pragma unroll
                for (int nj = 0; nj < 6; nj++) {
                    uint2 u = *(const uint2*)&g_wf[
                        (((size_t)(wn * 6 + nj) * 64 + kkg + 1) * 32 + lane) * 2];
                    bf[nb][nj][0] = u.x; bf[nb][nj][1] = u.y;
                }
            }
            uint32_t ah[2][4];
            const uint32_t acb = kt * 32 + (lane >> 4) * 16;   // bytes
            #pragma unroll
            for (int mi = 0; mi < 2; mi++)
                ldsm4(ah[mi], sx + (arow + mi * 16) * 144 + acb);

            const int cb_ = kkg & 1;
            #pragma unroll
            for (int mi = 0; mi < 2; mi++)
                #pragma unroll
                for (int nj = 0; nj < 6; nj++)
                    mma_f16(c[mi][nj], ah[mi], bf[cb_][nj][0], bf[cb_][nj][1]);
        }
    }

    // epilogue: fp32 frags -> fp16 q/k/v
    const float QSC = 0.03125f * 1.44269504088896f;  // (1/sqrt(1024))*log2(e)
    #pragma unroll
    for (int mi = 0; mi < 2; mi++) {
        int r0 = m0 + mi * 16 + (lane >> 2);
        #pragma unroll
        for (int nj = 0; nj < 6; nj++) {
            int nc = wn * 48 + nj * 8;
            int sel = nc >> 6;
            int col = (nc & 63) + (lane & 3) * 2;
            __half* dst = (sel == 0) ? g_q16 : (sel == 1 ? g_k16 : g_v16);
            float sc = (sel == 0) ? QSC : 1.0f;
            *(__half2*)&dst[(size_t)r0 * DH + col] =
                __floats2half2_rn(c[mi][nj][0] * sc, c[mi][nj][1] * sc);
            *(__half2*)&dst[(size_t)(r0 + 8) * DH + col] =
                __floats2half2_rn(c[mi][nj][2] * sc, c[mi][nj][3] * sc);
        }
    }
}

// ---------------------------------------------------------------------------
// Kernel 2: causal flash attention, fp16 mma.sync + 3-slot cp.async ring.
// Grid (32, 8) x 128 threads.  CTA handles qt = tile0 then 31-tile0 (33 iters).
// Softmax: exp2 domain, fp16x2 ex2; row-sum l via P.ones MMA (no shuffles).
// ONE barrier per iteration.  Dynamic smem 64512B.
// ---------------------------------------------------------------------------
#define ATT_STRIDE 72
#define ATT_TILE (64 * ATT_STRIDE)          // halves
#define ATT_TILE_B (ATT_TILE * 2)           // bytes (9216)

__global__ __launch_bounds__(128)
void attn_kernel(float* __restrict__ out)
{
    extern __shared__ __half smh[];
    const int t = threadIdx.x, lane = t & 31, w = t >> 5;
    const int tile0 = blockIdx.x, b = blockIdx.y;
    const size_t bb = (size_t)b * T_SEQ * DH;

    const uint32_t sq = smem_u32(smh);
    uint32_t skb[3], svb[3];
    #pragma unroll
    for (int i = 0; i < 3; i++) {
        skb[i] = sq + ATT_TILE_B * (1 + i);
        svb[i] = sq + ATT_TILE_B * (4 + i);
    }
    const int rl = lane >> 2, cb = (lane & 3) * 2;
    const uint32_t ONES = 0x3C003C00u;      // half2(1,1)

    // this thread's 4 slots within a 64x64 fp16 tile
    int soff[4];  // byte offset within a tile
    size_t gofs[4];
    #pragma unroll
    for (int i = 0; i < 4; i++) {
        int flat = t + i * 128;
        int r = flat >> 3, c8 = (flat & 7) * 8;
        soff[i] = (r * ATT_STRIDE + c8) * 2;
        gofs[i] = (size_t)r * DH + c8;
    }

    #pragma unroll
    for (int pass = 0; pass < 2; pass++) {
        const int qt = (pass == 0) ? tile0 : 31 - tile0;
        const int qbase = qt * 64;

        // prologue: Q + K0/V0 (group), then K1/V1 (group)
        #pragma unroll
        for (int i = 0; i < 4; i++) {
            cpa16(sq + soff[i], &g_q16[bb + (size_t)qbase * DH + gofs[i]]);
            cpa16(skb[0] + soff[i], &g_k16[bb + gofs[i]]);
            cpa16(svb[0] + soff[i], &g_v16[bb + gofs[i]]);
        }
        CPA_COMMIT();
        if (qt >= 1) {
            #pragma unroll
            for (int i = 0; i < 4; i++) {
                cpa16(skb[1] + soff[i], &g_k16[bb + 64 * DH + gofs[i]]);
                cpa16(svb[1] + soff[i], &g_v16[bb + 64 * DH + gofs[i]]);
            }
            CPA_COMMIT();
        }

        uint32_t qa[4][4];
        float o[8][4];
        #pragma unroll
        for (int nd = 0; nd < 8; nd++)
            #pragma unroll
            for (int q = 0; q < 4; q++) o[nd][q] = 0.0f;
        float m0v = -1e30f, m1v = -1e30f, l0v = 0.0f, l1v = 0.0f;

        for (int kt_ = 0; kt_ <= qt; kt_++) {
            if (kt_ < qt) { CPA_WAIT(1); } else { CPA_WAIT(0); }
            __syncthreads();

            // issue tile kt_+2 into ring slot (safe: its last readers finished
            // before the barrier we just passed)
            if (kt_ + 2 <= qt) {
                int sl = (kt_ + 2) % 3;
                size_t tb = bb + (size_t)(kt_ + 2) * 64 * DH;
                #pragma unroll
                for (int i = 0; i < 4; i++) {
                    cpa16(skb[sl] + soff[i], &g_k16[tb + gofs[i]]);
                    cpa16(svb[sl] + soff[i], &g_v16[tb + gofs[i]]);
                }
                CPA_COMMIT();
            }

            if (kt_ == 0) {   // Q resident; build A-fragments once per pass
                const uint32_t r_ = w * 16 + (lane & 7) + ((lane >> 3) & 1) * 8;
                #pragma unroll
                for (int kt = 0; kt < 4; kt++)
                    ldsm4(qa[kt], sq + r_ * 144 + (kt * 2 + (lane >> 4)) * 16);
            }

            const uint32_t sk = skb[kt_ % 3], sv = svb[kt_ % 3];

            // ---- S = Q . K^T  (log2-domain logits) ----
            float s[8][4];
            #pragma unroll
            for (int nt = 0; nt < 8; nt++) {
                #pragma unroll
                for (int q = 0; q < 4; q++) s[nt][q] = 0.0f;
                uint32_t kb[4];
                uint32_t base = sk + (nt * 8 + (lane & 7)) * 144;
                ldsm4(kb, base + (lane >> 3) * 16);          // d 0..31
                mma_f16(s[nt], qa[0], kb[0], kb[1]);
                mma_f16(s[nt], qa[1], kb[2], kb[3]);
                ldsm4(kb, base + (4 + (lane >> 3)) * 16);    // d 32..63
                mma_f16(s[nt], qa[2], kb[0], kb[1]);
                mma_f16(s[nt], qa[3], kb[2], kb[3]);
            }

            // ---- causal mask (diagonal tile only) ----
            if (kt_ == qt) {
                int r0 = w * 16 + rl, r1 = r0 + 8;
                #pragma unroll
                for (int nt = 0; nt < 8; nt++) {
                    int c0 = nt * 8 + cb;
                    if (c0     > r0) s[nt][0] = -1e30f;
                    if (c0 + 1 > r0) s[nt][1] = -1e30f;
                    if (c0     > r1) s[nt][2] = -1e30f;
                    if (c0 + 1 > r1) s[nt][3] = -1e30f;
                }
            }

            // ---- online softmax: max reduce fp32, exp in fp16x2 ----
            float mt0 = -1e30f, mt1 = -1e30f;
            #pragma unroll
            for (int nt = 0; nt < 8; nt++) {
                mt0 = fmaxf(mt0, fmaxf(s[nt][0], s[nt][1]));
                mt1 = fmaxf(mt1, fmaxf(s[nt][2], s[nt][3]));
            }
            #pragma unroll
            for (int off = 1; off <= 2; off <<= 1) {
                mt0 = fmaxf(mt0, __shfl_xor_sync(0xffffffffu, mt0, off));
                mt1 = fmaxf(mt1, __shfl_xor_sync(0xffffffffu, mt1, off));
            }
            float mn0 = fmaxf(m0v, mt0), mn1 = fmaxf(m1v, mt1);
            float f0 = ex2(m0v - mn0), f1 = ex2(m1v - mn1);
            m0v = mn0; m1v = mn1;

            uint32_t P0[8], P1[8];
            const uint32_t mn2_0 = ph2(mn0, mn0), mn2_1 = ph2(mn1, mn1);
            #pragma unroll
            for (int nt = 0; nt < 8; nt++) {
                P0[nt] = h2ex2(hsub2_(ph2(s[nt][0], s[nt][1]), mn2_0));
                P1[nt] = h2ex2(hsub2_(ph2(s[nt][2], s[nt][3]), mn2_1));
            }

            // rescale O
            #pragma unroll
            for (int nd = 0; nd < 8; nd++) {
                o[nd][0] *= f0; o[nd][1] *= f0;
                o[nd][2] *= f1; o[nd][3] *= f1;
            }

            // ---- O += P . V ;  l += P . 1 (row sums via MMA, fp32-exact) ----
            float cl[4] = {0.0f, 0.0f, 0.0f, 0.0f};
            #pragma unroll
            for (int kk = 0; kk < 4; kk++) {
                uint32_t pa[4] = {P0[2 * kk], P1[2 * kk],
                                  P0[2 * kk + 1], P1[2 * kk + 1]};
                mma_f16(cl, pa, ONES, ONES);   // row sums of this k16 slice
                uint32_t vbase = sv +
                    (kk * 16 + ((lane >> 3) & 1) * 8 + (lane & 7)) * 144 +
                    (lane >> 4) * 16;
                #pragma unroll
                for (int p = 0; p < 4; p++) {
                    uint32_t vb[4];
                    ldsm4t(vb, vbase + p * 32);
                    mma_f16(o[2 * p],     pa, vb[0], vb[1]);
                    mma_f16(o[2 * p + 1], pa, vb[2], vb[3]);
                }
            }
            l0v = l0v * f0 + cl[0];
            l1v = l1v * f1 + cl[2];
        }

        // ---- epilogue ----
        float inv0 = 1.0f / l0v, inv1 = 1.0f / l1v;
        int row0 = qbase + w * 16 + rl, row1 = row0 + 8;
        #pragma unroll
        for (int nd = 0; nd < 8; nd++) {
            int col = nd * 8 + cb;
            *(float2*)&out[bb + (size_t)row0 * DH + col] =
                make_float2(o[nd][0] * inv0, o[nd][1] * inv0);
            *(float2*)&out[bb + (size_t)row1 * DH + col] =
                make_float2(o[nd][2] * inv1, o[nd][3] * inv1);
        }
        __syncthreads();   // ring/Q reads done before next pass's cp.async
    }
}

// ---------------------------------------------------------------------------
// Launch
// ---------------------------------------------------------------------------
extern "C" void kernel_launch(void* const* d_in, const int* in_sizes, int n_in,
                              void* d_out, int out_size)
{
    (void)in_sizes; (void)n_in; (void)out_size;
    const float* x  = (const float*)d_in[0];
    const float* Wq = (const float*)d_in[1];
    const float* Wk = (const float*)d_in[2];
    const float* Wv = (const float*)d_in[3];
    float* out = (float*)d_out;

    wprep_kernel<<<96, 256>>>(Wq, Wk, Wv);
    qkv_kernel<<<M_TOTAL / 32, 128>>>(x);

    const int attn_smem = 7 * ATT_TILE_B;   // 64512
    cudaFuncSetAttribute(attn_kernel,
                         cudaFuncAttributeMaxDynamicSharedMemorySize, attn_smem);
    attn_kernel<<<dim3(32, BATCH), 128, attn_smem>>>(out);
}

// round 8
// speedup vs baseline: 5.7365x; 1.1971x over previous
#include <cuda_runtime.h>
#include <cuda_fp16.h>
#include <cstdint>

#define BATCH 8
#define T_SEQ 2048
#define DM 1024
#define DH 64
#define M_TOTAL (BATCH * T_SEQ)   // 16384

// ---------------------------------------------------------------------------
// Device scratch (no allocation allowed)
// ---------------------------------------------------------------------------
__device__ __align__(16) __half g_q16[M_TOTAL * DH];  // pre-scaled by log2e/32
__device__ __align__(16) __half g_k16[M_TOTAL * DH];
__device__ __align__(16) __half g_v16[M_TOTAL * DH];
// W in B-fragment order: [tn(24)][ktile(64)][lane(32)][reg(2)] of u32(fp16x2)
#define WF_FRAGS (24 * 64 * 32)
__device__ __align__(16) uint32_t g_wf[WF_FRAGS * 2];

// ---------------------------------------------------------------------------
// Helpers — sm_80-level PTX ONLY (plain sm_103 target: no 'a'-suffix features)
// ---------------------------------------------------------------------------
__device__ __forceinline__ uint32_t smem_u32(const void* p) {
    uint32_t a;
    asm("{ .reg .u64 t; cvta.to.shared.u64 t, %1; cvt.u32.u64 %0, t; }"
        : "=r"(a) : "l"(p));
    return a;
}
__device__ __forceinline__ void ldsm4(uint32_t r[4], uint32_t a) {
    asm volatile("ldmatrix.sync.aligned.m8n8.x4.shared.b16 {%0,%1,%2,%3}, [%4];"
                 : "=r"(r[0]), "=r"(r[1]), "=r"(r[2]), "=r"(r[3]) : "r"(a));
}
__device__ __forceinline__ void ldsm4t(uint32_t r[4], uint32_t a) {
    asm volatile("ldmatrix.sync.aligned.m8n8.x4.trans.shared.b16 {%0,%1,%2,%3}, [%4];"
                 : "=r"(r[0]), "=r"(r[1]), "=r"(r[2]), "=r"(r[3]) : "r"(a));
}
__device__ __forceinline__ void mma_f16(float c[4], const uint32_t a[4],
                                        uint32_t b0, uint32_t b1) {
    asm volatile(
        "mma.sync.aligned.m16n8k16.row.col.f32.f16.f16.f32 "
        "{%0,%1,%2,%3}, {%4,%5,%6,%7}, {%8,%9}, {%0,%1,%2,%3};"
        : "+f"(c[0]), "+f"(c[1]), "+f"(c[2]), "+f"(c[3])
        : "r"(a[0]), "r"(a[1]), "r"(a[2]), "r"(a[3]), "r"(b0), "r"(b1));
}
__device__ __forceinline__ uint32_t ph2(float a, float b) {   // low half = a
    __half2 h = __floats2half2_rn(a, b);
    return *reinterpret_cast<uint32_t*>(&h);
}
__device__ __forceinline__ float ex2(float x) {
    float y;
    asm("ex2.approx.f32 %0, %1;" : "=f"(y) : "f"(x));
    return y;
}
__device__ __forceinline__ uint32_t hsub2_(uint32_t a, uint32_t b) {
    uint32_t d;
    asm("sub.f16x2 %0, %1, %2;" : "=r"(d) : "r"(a), "r"(b));
    return d;
}
__device__ __forceinline__ uint32_t h2ex2(uint32_t x) {
    uint32_t y;
    asm("ex2.approx.f16x2 %0, %1;" : "=r"(y) : "r"(x));
    return y;
}
__device__ __forceinline__ void cpa16(uint32_t s, const void* g) {
    asm volatile("cp.async.cg.shared.global [%0], [%1], 16;"
                 :: "r"(s), "l"(g) : "memory");
}
#define CPA_COMMIT() asm volatile("cp.async.commit_group;" ::: "memory")
#define CPA_WAIT(n)  asm volatile("cp.async.wait_group %0;" :: "n"(n) : "memory")

// ---------------------------------------------------------------------------
// Kernel 0: W -> B-fragment-ordered fp16 (unchanged from R7).
// ---------------------------------------------------------------------------
__global__ __launch_bounds__(256)
void wprep_kernel(const float* __restrict__ Wq, const float* __restrict__ Wk,
                  const float* __restrict__ Wv)
{
    int tid = blockIdx.x * 256 + threadIdx.x;   // 24576 threads
    int nq = tid & 15, kp = (tid >> 4) & 511, m = tid >> 13;
    const float* W = (m == 0) ? Wq : (m == 1 ? Wk : Wv);
    int k = kp * 2, n0 = nq * 4;
    float4 a = *(const float4*)&W[k * DH + n0];
    float4 b = *(const float4*)&W[(k + 1) * DH + n0];
    int kt = k >> 4, r = (k >> 3) & 1, ksub = (k & 7) >> 1;
    const float* av = &a.x;
    const float* bv = &b.x;
    #pragma unroll
    for (int j = 0; j < 4; j++) {
        int np = m * 64 + n0 + j;
        int tn = np >> 3, lane = ((np & 7) << 2) | ksub;
        g_wf[(((size_t)tn * 64 + kt) * 32 + lane) * 2 + r] = ph2(av[j], bv[j]);
    }
}

// ---------------------------------------------------------------------------
// Kernel 1: QKV projection (unchanged from R7).
// 512 CTAs x 128 threads.  CTA tile 32(M) x 192(N), K=1024 in 16 chunks.
// ---------------------------------------------------------------------------
__global__ __launch_bounds__(128)
void qkv_kernel(const float* __restrict__ x)
{
    __shared__ __half xs[2][32 * 72];    // 144B rows

    const int t = threadIdx.x, lane = t & 31, wn = t >> 5;
    const int m0 = blockIdx.x * 32;
    const uint32_t sxb[2] = {smem_u32(xs[0]), smem_u32(xs[1])};

    float c[2][6][4];
    #pragma unroll
    for (int mi = 0; mi < 2; mi++)
        #pragma unroll
        for (int nj = 0; nj < 6; nj++)
            #pragma unroll
            for (int q = 0; q < 4; q++) c[mi][nj][q] = 0.0f;

    const int ld_row = t >> 2, ld_cb = (t & 3) * 16;
    const float* xbase = x + (size_t)(m0 + ld_row) * DM + ld_cb;

    float4 xr[4];
    #pragma unroll
    for (int i = 0; i < 4; i++) xr[i] = *(const float4*)(xbase + i * 4);

    uint32_t bf[2][6][2];
    #pragma unroll
    for (int nj = 0; nj < 6; nj++) {
        uint2 u = *(const uint2*)&g_wf[((size_t)(wn * 6 + nj) * 64) * 64 + lane * 2];
        bf[0][nj][0] = u.x; bf[0][nj][1] = u.y;
    }

    const uint32_t arow = (lane & 7) + ((lane >> 3) & 1) * 8;

    for (int cc = 0; cc < 16; cc++) {
        __half* xb = xs[cc & 1];
        #pragma unroll
        for (int i = 0; i < 2; i++) {
            float4 v0 = xr[2 * i], v1 = xr[2 * i + 1];
            *(uint4*)&xb[ld_row * 72 + ld_cb + i * 8] =
                make_uint4(ph2(v0.x, v0.y), ph2(v0.z, v0.w),
                           ph2(v1.x, v1.y), ph2(v1.z, v1.w));
        }
        __syncthreads();

        if (cc < 15) {
            const float* xp = xbase + (cc + 1) * 64;
            #pragma unroll
            for (int i = 0; i < 4; i++) xr[i] = *(const float4*)(xp + i * 4);
        }

        const uint32_t sx = sxb[cc & 1];
        #pragma unroll
        for (int kt = 0; kt < 4; kt++) {
            const int kkg = cc * 4 + kt;
            if (kkg < 63) {
                int nb = (kkg + 1) & 1;
                #pragma unroll
                for (int nj = 0; nj < 6; nj++) {
                    uint2 u = *(const uint2*)&g_wf[
                        (((size_t)(wn * 6 + nj) * 64 + kkg + 1) * 32 + lane) * 2];
                    bf[nb][nj][0] = u.x; bf[nb][nj][1] = u.y;
                }
            }
            uint32_t ah[2][4];
            const uint32_t acb = kt * 32 + (lane >> 4) * 16;   // bytes
            #pragma unroll
            for (int mi = 0; mi < 2; mi++)
                ldsm4(ah[mi], sx + (arow + mi * 16) * 144 + acb);

            const int cb_ = kkg & 1;
            #pragma unroll
            for (int mi = 0; mi < 2; mi++)
                #pragma unroll
                for (int nj = 0; nj < 6; nj++)
                    mma_f16(c[mi][nj], ah[mi], bf[cb_][nj][0], bf[cb_][nj][1]);
        }
    }

    const float QSC = 0.03125f * 1.44269504088896f;  // (1/sqrt(1024))*log2(e)
    #pragma unroll
    for (int mi = 0; mi < 2; mi++) {
        int r0 = m0 + mi * 16 + (lane >> 2);
        #pragma unroll
        for (int nj = 0; nj < 6; nj++) {
            int nc = wn * 48 + nj * 8;
            int sel = nc >> 6;
            int col = (nc & 63) + (lane & 3) * 2;
            __half* dst = (sel == 0) ? g_q16 : (sel == 1 ? g_k16 : g_v16);
            float sc = (sel == 0) ? QSC : 1.0f;
            *(__half2*)&dst[(size_t)r0 * DH + col] =
                __floats2half2_rn(c[mi][nj][0] * sc, c[mi][nj][1] * sc);
            *(__half2*)&dst[(size_t)(r0 + 8) * DH + col] =
                __floats2half2_rn(c[mi][nj][2] * sc, c[mi][nj][3] * sc);
        }
    }
}

// ---------------------------------------------------------------------------
// Kernel 2: causal flash attention — ONE (qt, batch) task per CTA (no more
// duplicated tiles), 256 CTAs, load-balanced bid->task map:
//   bids 108..147 (solo SMs under LUT[bid%148] placement): 40 heaviest tasks
//   bids (s, s+148) co-resident pairs: costs (27-a, a+1), sum 28.
// 128 threads, 3-slot cp.async ring, fp16x2 softmax, l via ones-MMA.
// ---------------------------------------------------------------------------
#define ATT_STRIDE 72
#define ATT_TILE (64 * ATT_STRIDE)          // halves
#define ATT_TILE_B (ATT_TILE * 2)           // bytes (9216)

__global__ __launch_bounds__(128)
void attn_kernel(float* __restrict__ out)
{
    extern __shared__ __half smh[];
    const int t = threadIdx.x, lane = t & 31, w = t >> 5;

    // ---- bid -> (qt, b) balanced task map ----
    const int bid = blockIdx.x;
    int qt, b;
    if (bid >= 108 && bid < 148) {          // solo SMs: heaviest tasks
        int i = bid - 108;                  // 0..39
        qt = 31 - (i >> 3);                 // 31..27
        b  = i & 7;
    } else if (bid < 108) {                 // first of co-resident pair
        if (bid < 104) { qt = 26 - (bid >> 3); b = bid & 7; }   // 26..14
        else           { qt = 13; b = bid - 104; }              // b 0..3
    } else {                                 // second of pair (bid-148)
        int p = bid - 148;                   // 0..107
        if (p < 104) { qt = p >> 3; b = p & 7; }                // 0..12
        else         { qt = 13; b = (p - 104) + 4; }            // b 4..7
    }
    const int qbase = qt * 64;
    const size_t bb = (size_t)b * T_SEQ * DH;

    const uint32_t sq = smem_u32(smh);
    uint32_t skb[3], svb[3];
    #pragma unroll
    for (int i = 0; i < 3; i++) {
        skb[i] = sq + ATT_TILE_B * (1 + i);
        svb[i] = sq + ATT_TILE_B * (4 + i);
    }
    const int rl = lane >> 2, cb = (lane & 3) * 2;
    const uint32_t ONES = 0x3C003C00u;      // half2(1,1)

    int soff[4];
    size_t gofs[4];
    #pragma unroll
    for (int i = 0; i < 4; i++) {
        int flat = t + i * 128;
        int r = flat >> 3, c8 = (flat & 7) * 8;
        soff[i] = (r * ATT_STRIDE + c8) * 2;
        gofs[i] = (size_t)r * DH + c8;
    }

    // prologue: Q + K0/V0 (group), then K1/V1 (group)
    #pragma unroll
    for (int i = 0; i < 4; i++) {
        cpa16(sq + soff[i], &g_q16[bb + (size_t)qbase * DH + gofs[i]]);
        cpa16(skb[0] + soff[i], &g_k16[bb + gofs[i]]);
        cpa16(svb[0] + soff[i], &g_v16[bb + gofs[i]]);
    }
    CPA_COMMIT();
    if (qt >= 1) {
        #pragma unroll
        for (int i = 0; i < 4; i++) {
            cpa16(skb[1] + soff[i], &g_k16[bb + 64 * DH + gofs[i]]);
            cpa16(svb[1] + soff[i], &g_v16[bb + 64 * DH + gofs[i]]);
        }
        CPA_COMMIT();
    }

    uint32_t qa[4][4];
    float o[8][4];
    #pragma unroll
    for (int nd = 0; nd < 8; nd++)
        #pragma unroll
        for (int q = 0; q < 4; q++) o[nd][q] = 0.0f;
    float m0v = -1e30f, m1v = -1e30f, l0v = 0.0f, l1v = 0.0f;

    for (int kt_ = 0; kt_ <= qt; kt_++) {
        if (kt_ < qt) { CPA_WAIT(1); } else { CPA_WAIT(0); }
        __syncthreads();

        // issue tile kt_+2 into ring slot
        if (kt_ + 2 <= qt) {
            int sl = (kt_ + 2) % 3;
            size_t tb = bb + (size_t)(kt_ + 2) * 64 * DH;
            #pragma unroll
            for (int i = 0; i < 4; i++) {
                cpa16(skb[sl] + soff[i], &g_k16[tb + gofs[i]]);
                cpa16(svb[sl] + soff[i], &g_v16[tb + gofs[i]]);
            }
            CPA_COMMIT();
        }

        if (kt_ == 0) {   // Q resident; build A-fragments once
            const uint32_t r_ = w * 16 + (lane & 7) + ((lane >> 3) & 1) * 8;
            #pragma unroll
            for (int kt = 0; kt < 4; kt++)
                ldsm4(qa[kt], sq + r_ * 144 + (kt * 2 + (lane >> 4)) * 16);
        }

        const uint32_t sk = skb[kt_ % 3], sv = svb[kt_ % 3];

        // ---- S = Q . K^T  (log2-domain logits) ----
        float s[8][4];
        #pragma unroll
        for (int nt = 0; nt < 8; nt++) {
            #pragma unroll
            for (int q = 0; q < 4; q++) s[nt][q] = 0.0f;
            uint32_t kb[4];
            uint32_t base = sk + (nt * 8 + (lane & 7)) * 144;
            ldsm4(kb, base + (lane >> 3) * 16);          // d 0..31
            mma_f16(s[nt], qa[0], kb[0], kb[1]);
            mma_f16(s[nt], qa[1], kb[2], kb[3]);
            ldsm4(kb, base + (4 + (lane >> 3)) * 16);    // d 32..63
            mma_f16(s[nt], qa[2], kb[0], kb[1]);
            mma_f16(s[nt], qa[3], kb[2], kb[3]);
        }

        // ---- causal mask (diagonal tile only) ----
        if (kt_ == qt) {
            int r0 = w * 16 + rl, r1 = r0 + 8;
            #pragma unroll
            for (int nt = 0; nt < 8; nt++) {
                int c0 = nt * 8 + cb;
                if (c0     > r0) s[nt][0] = -1e30f;
                if (c0 + 1 > r0) s[nt][1] = -1e30f;
                if (c0     > r1) s[nt][2] = -1e30f;
                if (c0 + 1 > r1) s[nt][3] = -1e30f;
            }
        }

        // ---- online softmax: max reduce fp32, exp in fp16x2 ----
        float mt0 = -1e30f, mt1 = -1e30f;
        #pragma unroll
        for (int nt = 0; nt < 8; nt++) {
            mt0 = fmaxf(mt0, fmaxf(s[nt][0], s[nt][1]));
            mt1 = fmaxf(mt1, fmaxf(s[nt][2], s[nt][3]));
        }
        #pragma unroll
        for (int off = 1; off <= 2; off <<= 1) {
            mt0 = fmaxf(mt0, __shfl_xor_sync(0xffffffffu, mt0, off));
            mt1 = fmaxf(mt1, __shfl_xor_sync(0xffffffffu, mt1, off));
        }
        float mn0 = fmaxf(m0v, mt0), mn1 = fmaxf(m1v, mt1);
        float f0 = ex2(m0v - mn0), f1 = ex2(m1v - mn1);
        m0v = mn0; m1v = mn1;

        uint32_t P0[8], P1[8];
        const uint32_t mn2_0 = ph2(mn0, mn0), mn2_1 = ph2(mn1, mn1);
        #pragma unroll
        for (int nt = 0; nt < 8; nt++) {
            P0[nt] = h2ex2(hsub2_(ph2(s[nt][0], s[nt][1]), mn2_0));
            P1[nt] = h2ex2(hsub2_(ph2(s[nt][2], s[nt][3]), mn2_1));
        }

        // rescale O
        #pragma unroll
        for (int nd = 0; nd < 8; nd++) {
            o[nd][0] *= f0; o[nd][1] *= f0;
            o[nd][2] *= f1; o[nd][3] *= f1;
        }

        // ---- O += P . V ;  l += P . 1 (row sums via MMA) ----
        float cl[4] = {0.0f, 0.0f, 0.0f, 0.0f};
        #pragma unroll
        for (int kk = 0; kk < 4; kk++) {
            uint32_t pa[4] = {P0[2 * kk], P1[2 * kk],
                              P0[2 * kk + 1], P1[2 * kk + 1]};
            mma_f16(cl, pa, ONES, ONES);
            uint32_t vbase = sv +
                (kk * 16 + ((lane >> 3) & 1) * 8 + (lane & 7)) * 144 +
                (lane >> 4) * 16;
            #pragma unroll
            for (int p = 0; p < 4; p++) {
                uint32_t vb[4];
                ldsm4t(vb, vbase + p * 32);
                mma_f16(o[2 * p],     pa, vb[0], vb[1]);
                mma_f16(o[2 * p + 1], pa, vb[2], vb[3]);
            }
        }
        l0v = l0v * f0 + cl[0];
        l1v = l1v * f1 + cl[2];
    }

    // ---- epilogue ----
    float inv0 = 1.0f / l0v, inv1 = 1.0f / l1v;
    int row0 = qbase + w * 16 + rl, row1 = row0 + 8;
    #pragma unroll
    for (int nd = 0; nd < 8; nd++) {
        int col = nd * 8 + cb;
        *(float2*)&out[bb + (size_t)row0 * DH + col] =
            make_float2(o[nd][0] * inv0, o[nd][1] * inv0);
        *(float2*)&out[bb + (size_t)row1 * DH + col] =
            make_float2(o[nd][2] * inv1, o[nd][3] * inv1);
    }
}

// ---------------------------------------------------------------------------
// Launch
// ---------------------------------------------------------------------------
extern "C" void kernel_launch(void* const* d_in, const int* in_sizes, int n_in,
                              void* d_out, int out_size)
{
    (void)in_sizes; (void)n_in; (void)out_size;
    const float* x  = (const float*)d_in[0];
    const float* Wq = (const float*)d_in[1];
    const float* Wk = (const float*)d_in[2];
    const float* Wv = (const float*)d_in[3];
    float* out = (float*)d_out;

    wprep_kernel<<<96, 256>>>(Wq, Wk, Wv);
    qkv_kernel<<<M_TOTAL / 32, 128>>>(x);

    const int attn_smem = 7 * ATT_TILE_B;   // 64512
    cudaFuncSetAttribute(attn_kernel,
                         cudaFuncAttributeMaxDynamicSharedMemorySize, attn_smem);
    attn_kernel<<<256, 128, attn_smem>>>(out);
}

// round 9
// speedup vs baseline: 6.3619x; 1.1090x over previous
#include <cuda_runtime.h>
#include <cuda_fp16.h>
#include <cstdint>

#define BATCH 8
#define T_SEQ 2048
#define DM 1024
#define DH 64
#define M_TOTAL (BATCH * T_SEQ)   // 16384

// ---------------------------------------------------------------------------
// Device scratch (no allocation allowed)
// ---------------------------------------------------------------------------
__device__ __align__(16) __half g_q16[M_TOTAL * DH];  // pre-scaled by log2e/32
__device__ __align__(16) __half g_k16[M_TOTAL * DH];
__device__ __align__(16) __half g_v16[M_TOTAL * DH];
#define WF_FRAGS (24 * 64 * 32)
__device__ __align__(16) uint32_t g_wf[WF_FRAGS * 2];

// split-K partials: 40 slots = (qt-27)*8 + b
__device__ __align__(16) float g_pO[40][64 * 64];
__device__ float g_pm[40][64];
__device__ float g_pl[40][64];
__device__ unsigned g_pflag[40];

// ---------------------------------------------------------------------------
// Helpers — sm_80-level PTX ONLY
// ---------------------------------------------------------------------------
__device__ __forceinline__ uint32_t smem_u32(const void* p) {
    uint32_t a;
    asm("{ .reg .u64 t; cvta.to.shared.u64 t, %1; cvt.u32.u64 %0, t; }"
        : "=r"(a) : "l"(p));
    return a;
}
__device__ __forceinline__ void ldsm4(uint32_t r[4], uint32_t a) {
    asm volatile("ldmatrix.sync.aligned.m8n8.x4.shared.b16 {%0,%1,%2,%3}, [%4];"
                 : "=r"(r[0]), "=r"(r[1]), "=r"(r[2]), "=r"(r[3]) : "r"(a));
}
__device__ __forceinline__ void ldsm4t(uint32_t r[4], uint32_t a) {
    asm volatile("ldmatrix.sync.aligned.m8n8.x4.trans.shared.b16 {%0,%1,%2,%3}, [%4];"
                 : "=r"(r[0]), "=r"(r[1]), "=r"(r[2]), "=r"(r[3]) : "r"(a));
}
__device__ __forceinline__ void mma_f16(float c[4], const uint32_t a[4],
                                        uint32_t b0, uint32_t b1) {
    asm volatile(
        "mma.sync.aligned.m16n8k16.row.col.f32.f16.f16.f32 "
        "{%0,%1,%2,%3}, {%4,%5,%6,%7}, {%8,%9}, {%0,%1,%2,%3};"
        : "+f"(c[0]), "+f"(c[1]), "+f"(c[2]), "+f"(c[3])
        : "r"(a[0]), "r"(a[1]), "r"(a[2]), "r"(a[3]), "r"(b0), "r"(b1));
}
__device__ __forceinline__ uint32_t ph2(float a, float b) {
    __half2 h = __floats2half2_rn(a, b);
    return *reinterpret_cast<uint32_t*>(&h);
}
__device__ __forceinline__ float ex2(float x) {
    float y;
    asm("ex2.approx.f32 %0, %1;" : "=f"(y) : "f"(x));
    return y;
}
__device__ __forceinline__ uint32_t hsub2_(uint32_t a, uint32_t b) {
    uint32_t d;
    asm("sub.f16x2 %0, %1, %2;" : "=r"(d) : "r"(a), "r"(b));
    return d;
}
__device__ __forceinline__ uint32_t h2ex2(uint32_t x) {
    uint32_t y;
    asm("ex2.approx.f16x2 %0, %1;" : "=r"(y) : "r"(x));
    return y;
}
__device__ __forceinline__ void cpa16(uint32_t s, const void* g) {
    asm volatile("cp.async.cg.shared.global [%0], [%1], 16;"
                 :: "r"(s), "l"(g) : "memory");
}
#define CPA_COMMIT() asm volatile("cp.async.commit_group;" ::: "memory")
#define CPA_WAIT(n)  asm volatile("cp.async.wait_group %0;" :: "n"(n) : "memory")

// ---------------------------------------------------------------------------
// Task table: 37 tasks per batch, sorted by cost (k1-k0) descending.
// qt 27..31 are split into two key-range chunks (A=[0,h), B=[h,qt+1)).
// Pairing rank r with rank 36-r gives pair sums 28..30.
// ---------------------------------------------------------------------------
static __device__ const signed char T_QT[37] = {
    26,25,24,23,22,21,20,19,18,17,16,        // r0-10  singles, cost 27..17
    15, 31,31,30,                            // r11-14 cost 16
    14, 30,29,29,28,                         // r15-19 cost 15
    13, 28,27,27,                            // r20-23 cost 14
    12,11,10,9,8,7,6,5,4,3,2,1,0             // r24-36 cost 13..1
};
static __device__ const signed char T_K0[37] = {
    0,0,0,0,0,0,0,0,0,0,0,
    0, 0,16,0,
    0, 16,0,15,0,
    0, 15,0,14,
    0,0,0,0,0,0,0,0,0,0,0,0,0
};
static __device__ const signed char T_K1[37] = {
    27,26,25,24,23,22,21,20,19,18,17,
    16, 16,32,16,
    15, 31,15,30,15,
    14, 29,14,28,
    13,12,11,10,9,8,7,6,5,4,3,2,1
};

// ---------------------------------------------------------------------------
// Kernel 0: W -> B-fragment-ordered fp16; also resets split-combine flags.
// ---------------------------------------------------------------------------
__global__ __launch_bounds__(256)
void wprep_kernel(const float* __restrict__ Wq, const float* __restrict__ Wk,
                  const float* __restrict__ Wv)
{
    if (blockIdx.x == 0 && threadIdx.x < 40) g_pflag[threadIdx.x] = 0u;

    int tid = blockIdx.x * 256 + threadIdx.x;   // 24576 threads
    int nq = tid & 15, kp = (tid >> 4) & 511, m = tid >> 13;
    const float* W = (m == 0) ? Wq : (m == 1 ? Wk : Wv);
    int k = kp * 2, n0 = nq * 4;
    float4 a = *(const float4*)&W[k * DH + n0];
    float4 b = *(const float4*)&W[(k + 1) * DH + n0];
    int kt = k >> 4, r = (k >> 3) & 1, ksub = (k & 7) >> 1;
    const float* av = &a.x;
    const float* bv = &b.x;
    #pragma unroll
    for (int j = 0; j < 4; j++) {
        int np = m * 64 + n0 + j;
        int tn = np >> 3, lane = ((np & 7) << 2) | ksub;
        g_wf[(((size_t)tn * 64 + kt) * 32 + lane) * 2 + r] = ph2(av[j], bv[j]);
    }
}

// ---------------------------------------------------------------------------
// Kernel 1: QKV projection (unchanged from R8).
// ---------------------------------------------------------------------------
__global__ __launch_bounds__(128)
void qkv_kernel(const float* __restrict__ x)
{
    __shared__ __half xs[2][32 * 72];

    const int t = threadIdx.x, lane = t & 31, wn = t >> 5;
    const int m0 = blockIdx.x * 32;
    const uint32_t sxb[2] = {smem_u32(xs[0]), smem_u32(xs[1])};

    float c[2][6][4];
    #pragma unroll
    for (int mi = 0; mi < 2; mi++)
        #pragma unroll
        for (int nj = 0; nj < 6; nj++)
            #pragma unroll
            for (int q = 0; q < 4; q++) c[mi][nj][q] = 0.0f;

    const int ld_row = t >> 2, ld_cb = (t & 3) * 16;
    const float* xbase = x + (size_t)(m0 + ld_row) * DM + ld_cb;

    float4 xr[4];
    #pragma unroll
    for (int i = 0; i < 4; i++) xr[i] = *(const float4*)(xbase + i * 4);

    uint32_t bf[2][6][2];
    #pragma unroll
    for (int nj = 0; nj < 6; nj++) {
        uint2 u = *(const uint2*)&g_wf[((size_t)(wn * 6 + nj) * 64) * 64 + lane * 2];
        bf[0][nj][0] = u.x; bf[0][nj][1] = u.y;
    }

    const uint32_t arow = (lane & 7) + ((lane >> 3) & 1) * 8;

    for (int cc = 0; cc < 16; cc++) {
        __half* xb = xs[cc & 1];
        #pragma unroll
        for (int i = 0; i < 2; i++) {
            float4 v0 = xr[2 * i], v1 = xr[2 * i + 1];
            *(uint4*)&xb[ld_row * 72 + ld_cb + i * 8] =
                make_uint4(ph2(v0.x, v0.y), ph2(v0.z, v0.w),
                           ph2(v1.x, v1.y), ph2(v1.z, v1.w));
        }
        __syncthreads();

        if (cc < 15) {
            const float* xp = xbase + (cc + 1) * 64;
            #pragma unroll
            for (int i = 0; i < 4; i++) xr[i] = *(const float4*)(xp + i * 4);
        }

        const uint32_t sx = sxb[cc & 1];
        #pragma unroll
        for (int kt = 0; kt < 4; kt++) {
            const int kkg = cc * 4 + kt;
            if (kkg < 63) {
                int nb = (kkg + 1) & 1;
                #pragma unroll
                for (int nj = 0; nj < 6; nj++) {
                    uint2 u = *(const uint2*)&g_wf[
                        (((size_t)(wn * 6 + nj) * 64 + kkg + 1) * 32 + lane) * 2];
                    bf[nb][nj][0] = u.x; bf[nb][nj][1] = u.y;
                }
            }
            uint32_t ah[2][4];
            const uint32_t acb = kt * 32 + (lane >> 4) * 16;
            #pragma unroll
            for (int mi = 0; mi < 2; mi++)
                ldsm4(ah[mi], sx + (arow + mi * 16) * 144 + acb);

            const int cb_ = kkg & 1;
            #pragma unroll
            for (int mi = 0; mi < 2; mi++)
                #pragma unroll
                for (int nj = 0; nj < 6; nj++)
                    mma_f16(c[mi][nj], ah[mi], bf[cb_][nj][0], bf[cb_][nj][1]);
        }
    }

    const float QSC = 0.03125f * 1.44269504088896f;
    #pragma unroll
    for (int mi = 0; mi < 2; mi++) {
        int r0 = m0 + mi * 16 + (lane >> 2);
        #pragma unroll
        for (int nj = 0; nj < 6; nj++) {
            int nc = wn * 48 + nj * 8;
            int sel = nc >> 6;
            int col = (nc & 63) + (lane & 3) * 2;
            __half* dst = (sel == 0) ? g_q16 : (sel == 1 ? g_k16 : g_v16);
            float sc = (sel == 0) ? QSC : 1.0f;
            *(__half2*)&dst[(size_t)r0 * DH + col] =
                __floats2half2_rn(c[mi][nj][0] * sc, c[mi][nj][1] * sc);
            *(__half2*)&dst[(size_t)(r0 + 8) * DH + col] =
                __floats2half2_rn(c[mi][nj][2] * sc, c[mi][nj][3] * sc);
        }
    }
}

// ---------------------------------------------------------------------------
// Kernel 2: causal flash attention, 296 CTAs (2 per SM, pair-sum-balanced).
// Split tasks (qt>=27) combine partials via gmem scratch + flag.
// ---------------------------------------------------------------------------
#define ATT_STRIDE 72
#define ATT_TILE (64 * ATT_STRIDE)
#define ATT_TILE_B (ATT_TILE * 2)

__global__ __launch_bounds__(128)
void attn_kernel(float* __restrict__ out)
{
    extern __shared__ __half smh[];
    const int t = threadIdx.x, lane = t & 31, w = t >> 5;

    // bid -> global sorted index g -> (rank, batch) -> task
    const int bid = blockIdx.x;
    const int g = (bid < 148) ? bid : (443 - bid);
    const int rank = g >> 3, b = g & 7;
    const int qt  = T_QT[rank];
    const int kt0 = T_K0[rank];
    const int kt1 = T_K1[rank];
    const bool isSplit = (qt >= 27);
    const bool isA = isSplit && (kt0 == 0);
    const bool isB = isSplit && (kt0 != 0);
    const int sid = (qt - 27) * 8 + b;   // valid only when isSplit

    const int qbase = qt * 64;
    const size_t bb = (size_t)b * T_SEQ * DH;

    const uint32_t sq = smem_u32(smh);
    uint32_t skb[3], svb[3];
    #pragma unroll
    for (int i = 0; i < 3; i++) {
        skb[i] = sq + ATT_TILE_B * (1 + i);
        svb[i] = sq + ATT_TILE_B * (4 + i);
    }
    const int rl = lane >> 2, cb = (lane & 3) * 2;
    const uint32_t ONES = 0x3C003C00u;

    int soff[4];
    size_t gofs[4];
    #pragma unroll
    for (int i = 0; i < 4; i++) {
        int flat = t + i * 128;
        int r = flat >> 3, c8 = (flat & 7) * 8;
        soff[i] = (r * ATT_STRIDE + c8) * 2;
        gofs[i] = (size_t)r * DH + c8;
    }

    // prologue: Q + K/V tile kt0 (group), then kt0+1 (group)
    #pragma unroll
    for (int i = 0; i < 4; i++) {
        cpa16(sq + soff[i], &g_q16[bb + (size_t)qbase * DH + gofs[i]]);
        cpa16(skb[kt0 % 3] + soff[i], &g_k16[bb + (size_t)kt0 * 64 * DH + gofs[i]]);
        cpa16(svb[kt0 % 3] + soff[i], &g_v16[bb + (size_t)kt0 * 64 * DH + gofs[i]]);
    }
    CPA_COMMIT();
    if (kt0 + 1 < kt1) {
        #pragma unroll
        for (int i = 0; i < 4; i++) {
            size_t src = bb + (size_t)(kt0 + 1) * 64 * DH + gofs[i];
            cpa16(skb[(kt0 + 1) % 3] + soff[i], &g_k16[src]);
            cpa16(svb[(kt0 + 1) % 3] + soff[i], &g_v16[src]);
        }
        CPA_COMMIT();
    }

    uint32_t qa[4][4];
    float o[8][4];
    #pragma unroll
    for (int nd = 0; nd < 8; nd++)
        #pragma unroll
        for (int q = 0; q < 4; q++) o[nd][q] = 0.0f;
    float m0v = -1e30f, m1v = -1e30f, l0v = 0.0f, l1v = 0.0f;

    for (int kt_ = kt0; kt_ < kt1; kt_++) {
        if (kt_ < kt1 - 1) { CPA_WAIT(1); } else { CPA_WAIT(0); }
        __syncthreads();

        if (kt_ + 2 < kt1) {
            int sl = (kt_ + 2) % 3;
            size_t tb = bb + (size_t)(kt_ + 2) * 64 * DH;
            #pragma unroll
            for (int i = 0; i < 4; i++) {
                cpa16(skb[sl] + soff[i], &g_k16[tb + gofs[i]]);
                cpa16(svb[sl] + soff[i], &g_v16[tb + gofs[i]]);
            }
            CPA_COMMIT();
        }

        if (kt_ == kt0) {   // Q resident; build A-fragments once
            const uint32_t r_ = w * 16 + (lane & 7) + ((lane >> 3) & 1) * 8;
            #pragma unroll
            for (int kt = 0; kt < 4; kt++)
                ldsm4(qa[kt], sq + r_ * 144 + (kt * 2 + (lane >> 4)) * 16);
        }

        const uint32_t sk = skb[kt_ % 3], sv = svb[kt_ % 3];

        // ---- S = Q . K^T ----
        float s[8][4];
        #pragma unroll
        for (int nt = 0; nt < 8; nt++) {
            #pragma unroll
            for (int q = 0; q < 4; q++) s[nt][q] = 0.0f;
            uint32_t kb[4];
            uint32_t base = sk + (nt * 8 + (lane & 7)) * 144;
            ldsm4(kb, base + (lane >> 3) * 16);
            mma_f16(s[nt], qa[0], kb[0], kb[1]);
            mma_f16(s[nt], qa[1], kb[2], kb[3]);
            ldsm4(kb, base + (4 + (lane >> 3)) * 16);
            mma_f16(s[nt], qa[2], kb[0], kb[1]);
            mma_f16(s[nt], qa[3], kb[2], kb[3]);
        }

        // ---- causal mask (diagonal tile only) ----
        if (kt_ == qt) {
            int r0 = w * 16 + rl, r1 = r0 + 8;
            #pragma unroll
            for (int nt = 0; nt < 8; nt++) {
                int c0 = nt * 8 + cb;
                if (c0     > r0) s[nt][0] = -1e30f;
                if (c0 + 1 > r0) s[nt][1] = -1e30f;
                if (c0     > r1) s[nt][2] = -1e30f;
                if (c0 + 1 > r1) s[nt][3] = -1e30f;
            }
        }

        // ---- online softmax ----
        float mt0 = -1e30f, mt1 = -1e30f;
        #pragma unroll
        for (int nt = 0; nt < 8; nt++) {
            mt0 = fmaxf(mt0, fmaxf(s[nt][0], s[nt][1]));
            mt1 = fmaxf(mt1, fmaxf(s[nt][2], s[nt][3]));
        }
        #pragma unroll
        for (int off = 1; off <= 2; off <<= 1) {
            mt0 = fmaxf(mt0, __shfl_xor_sync(0xffffffffu, mt0, off));
            mt1 = fmaxf(mt1, __shfl_xor_sync(0xffffffffu, mt1, off));
        }
        float mn0 = fmaxf(m0v, mt0), mn1 = fmaxf(m1v, mt1);
        float f0 = ex2(m0v - mn0), f1 = ex2(m1v - mn1);
        m0v = mn0; m1v = mn1;

        uint32_t P0[8], P1[8];
        const uint32_t mn2_0 = ph2(mn0, mn0), mn2_1 = ph2(mn1, mn1);
        #pragma unroll
        for (int nt = 0; nt < 8; nt++) {
            P0[nt] = h2ex2(hsub2_(ph2(s[nt][0], s[nt][1]), mn2_0));
            P1[nt] = h2ex2(hsub2_(ph2(s[nt][2], s[nt][3]), mn2_1));
        }

        #pragma unroll
        for (int nd = 0; nd < 8; nd++) {
            o[nd][0] *= f0; o[nd][1] *= f0;
            o[nd][2] *= f1; o[nd][3] *= f1;
        }

        // ---- O += P.V ; l += P.1 ----
        float cl[4] = {0.0f, 0.0f, 0.0f, 0.0f};
        #pragma unroll
        for (int kk = 0; kk < 4; kk++) {
            uint32_t pa[4] = {P0[2 * kk], P1[2 * kk],
                              P0[2 * kk + 1], P1[2 * kk + 1]};
            mma_f16(cl, pa, ONES, ONES);
            uint32_t vbase = sv +
                (kk * 16 + ((lane >> 3) & 1) * 8 + (lane & 7)) * 144 +
                (lane >> 4) * 16;
            #pragma unroll
            for (int p = 0; p < 4; p++) {
                uint32_t vb[4];
                ldsm4t(vb, vbase + p * 32);
                mma_f16(o[2 * p],     pa, vb[0], vb[1]);
                mma_f16(o[2 * p + 1], pa, vb[2], vb[3]);
            }
        }
        l0v = l0v * f0 + cl[0];
        l1v = l1v * f1 + cl[2];
    }

    // ---- epilogue ----
    const int row0l = w * 16 + rl, row1l = row0l + 8;
    const int row0 = qbase + row0l, row1 = qbase + row1l;

    if (isA) {
        // write unnormalized partial (O, m, l) and release flag
        float* PO = g_pO[sid];
        #pragma unroll
        for (int nd = 0; nd < 8; nd++) {
            int col = nd * 8 + cb;
            *(float2*)&PO[row0l * 64 + col] = make_float2(o[nd][0], o[nd][1]);
            *(float2*)&PO[row1l * 64 + col] = make_float2(o[nd][2], o[nd][3]);
        }
        if ((lane & 3) == 0) {
            g_pm[sid][row0l] = m0v;  g_pl[sid][row0l] = l0v;
            g_pm[sid][row1l] = m1v;  g_pl[sid][row1l] = l1v;
        }
        __syncthreads();
        if (t == 0) {
            __threadfence();
            atomicExch(&g_pflag[sid], 1u);
        }
    } else if (isB) {
        // acquire partner's partial, merge, write final
        if (t == 0) {
            while (atomicAdd(&g_pflag[sid], 0u) == 0u) __nanosleep(64);
            __threadfence();
        }
        __syncthreads();
        const float mA0 = g_pm[sid][row0l], lA0 = g_pl[sid][row0l];
        const float mA1 = g_pm[sid][row1l], lA1 = g_pl[sid][row1l];
        const float mm0 = fmaxf(m0v, mA0), mm1 = fmaxf(m1v, mA1);
        const float fB0 = ex2(m0v - mm0), fA0 = ex2(mA0 - mm0);
        const float fB1 = ex2(m1v - mm1), fA1 = ex2(mA1 - mm1);
        const float il0 = 1.0f / (l0v * fB0 + lA0 * fA0);
        const float il1 = 1.0f / (l1v * fB1 + lA1 * fA1);
        const float* PO = g_pO[sid];
        #pragma unroll
        for (int nd = 0; nd < 8; nd++) {
            int col = nd * 8 + cb;
            float2 a0 = *(const float2*)&PO[row0l * 64 + col];
            float2 a1 = *(const float2*)&PO[row1l * 64 + col];
            *(float2*)&out[bb + (size_t)row0 * DH + col] =
                make_float2((o[nd][0] * fB0 + a0.x * fA0) * il0,
                            (o[nd][1] * fB0 + a0.y * fA0) * il0);
            *(float2*)&out[bb + (size_t)row1 * DH + col] =
                make_float2((o[nd][2] * fB1 + a1.x * fA1) * il1,
                            (o[nd][3] * fB1 + a1.y * fA1) * il1);
        }
    } else {
        const float inv0 = 1.0f / l0v, inv1 = 1.0f / l1v;
        #pragma unroll
        for (int nd = 0; nd < 8; nd++) {
            int col = nd * 8 + cb;
            *(float2*)&out[bb + (size_t)row0 * DH + col] =
                make_float2(o[nd][0] * inv0, o[nd][1] * inv0);
            *(float2*)&out[bb + (size_t)row1 * DH + col] =
                make_float2(o[nd][2] * inv1, o[nd][3] * inv1);
        }
    }
}

// ---------------------------------------------------------------------------
// Launch
// ---------------------------------------------------------------------------
extern "C" void kernel_launch(void* const* d_in, const int* in_sizes, int n_in,
                              void* d_out, int out_size)
{
    (void)in_sizes; (void)n_in; (void)out_size;
    const float* x  = (const float*)d_in[0];
    const float* Wq = (const float*)d_in[1];
    const float* Wk = (const float*)d_in[2];
    const float* Wv = (const float*)d_in[3];
    float* out = (float*)d_out;

    wprep_kernel<<<96, 256>>>(Wq, Wk, Wv);
    qkv_kernel<<<M_TOTAL / 32, 128>>>(x);

    const int attn_smem = 7 * ATT_TILE_B;   // 64512
    cudaFuncSetAttribute(attn_kernel,
                         cudaFuncAttributeMaxDynamicSharedMemorySize, attn_smem);
    attn_kernel<<<296, 128, attn_smem>>>(out);
}